// round 4
// baseline (speedup 1.0000x reference)
#include <cuda_runtime.h>
#include <stdint.h>

// Problem dims
#define Bn 2
#define Tn 2048
#define Cn 1024
#define Hn 16
#define HDn 64
#define Mrows (Bn * Tn)   // 4096

// Scratch (allocation-free: __device__ globals)
__device__ float g_q[Bn * Hn * Tn * HDn];   // tf32-rounded, pre-scaled by 1/8
__device__ float g_k[Bn * Hn * Tn * HDn];   // tf32-rounded
__device__ float g_v[Bn * Hn * Tn * HDn];   // tf32-rounded
__device__ float g_a[Bn * Tn * Cn];         // flash out, tf32-rounded
__device__ uint32_t g_xt[Mrows * Cn];       // x  pre-rounded to tf32
__device__ uint32_t g_wqt[Cn * Cn];
__device__ uint32_t g_wkt[Cn * Cn];
__device__ uint32_t g_wvt[Cn * Cn];
__device__ uint32_t g_wpt[Cn * Cn];

__device__ __forceinline__ uint32_t f2tf32(float x) {
    uint32_t y;
    asm("cvt.rna.tf32.f32 %0, %1;" : "=r"(y) : "f"(x));
    return y;
}

__device__ __forceinline__ void mma_tf32(float* c, const uint32_t* a,
                                         uint32_t b0, uint32_t b1) {
    asm volatile(
        "mma.sync.aligned.m16n8k8.row.col.f32.tf32.tf32.f32 "
        "{%0,%1,%2,%3}, {%4,%5,%6,%7}, {%8,%9}, {%0,%1,%2,%3};"
        : "+f"(c[0]), "+f"(c[1]), "+f"(c[2]), "+f"(c[3])
        : "r"(a[0]), "r"(a[1]), "r"(a[2]), "r"(a[3]), "r"(b0), "r"(b1));
}

__device__ __forceinline__ void cpa16(uint32_t dst, const void* src) {
    asm volatile("cp.async.ca.shared.global [%0], [%1], 16;" :: "r"(dst), "l"(src));
}
#define CP_COMMIT() asm volatile("cp.async.commit_group;")
#define CP_WAIT1()  asm volatile("cp.async.wait_group 1;")

// ---------------------------------------------------------------------------
// prep: round x and the 4 weights to tf32 once (vectorized).
//   float4 counts: x = 1M, each W = 256K -> 2M total.
// ---------------------------------------------------------------------------
__global__ __launch_bounds__(256)
void prep_cvt(const float4* __restrict__ x,
              const float4* __restrict__ wq, const float4* __restrict__ wk,
              const float4* __restrict__ wv, const float4* __restrict__ wp,
              uint4* __restrict__ xt,
              uint4* __restrict__ wqt, uint4* __restrict__ wkt,
              uint4* __restrict__ wvt, uint4* __restrict__ wpt)
{
    const int i = blockIdx.x * 256 + threadIdx.x;   // 0 .. 2M-1
    const float4* src; uint4* dst; int off;
    if (i < (1 << 20))            { src = x;  dst = xt;  off = i; }
    else if (i < (1 << 20) + (1 << 18))     { src = wq; dst = wqt; off = i - (1 << 20); }
    else if (i < (1 << 20) + 2 * (1 << 18)) { src = wk; dst = wkt; off = i - (1 << 20) - (1 << 18); }
    else if (i < (1 << 20) + 3 * (1 << 18)) { src = wv; dst = wvt; off = i - (1 << 20) - 2 * (1 << 18); }
    else                                    { src = wp; dst = wpt; off = i - (1 << 20) - 3 * (1 << 18); }
    float4 v = src[off];
    uint4 u = {f2tf32(v.x), f2tf32(v.y), f2tf32(v.z), f2tf32(v.w)};
    dst[off] = u;
}

// ---------------------------------------------------------------------------
// tf32 GEMM v2: D = (A @ W^T + bias) * scale ; A, W already tf32-rounded.
//   128x128 block, 4 warps (64x64 warp tile), BK=16, 3-stage cp.async.
//   MODE 0: scatter into [B,H,T,64] with tf32 rounding of output.
//   MODE 1: plain row-major fp32 output.
// ---------------------------------------------------------------------------
#define SST 20
#define STG_W (128 * SST)               // 2560 words per tensor per stage
#define GEMM_SMEM (3 * 2 * STG_W * 4)   // 61440 bytes

template <int MODE>
__global__ __launch_bounds__(128)
void tf32_gemm2(const uint32_t* __restrict__ A, const uint32_t* __restrict__ W,
                const float* __restrict__ bias, float* __restrict__ D,
                float scale)
{
    extern __shared__ uint32_t smem[];
    const int tid  = threadIdx.x;
    const int lane = tid & 31;
    const int wid  = tid >> 5;             // 0..3
    const int m0   = blockIdx.y * 128;
    const int n0   = blockIdx.x * 128;
    const int wm   = (wid & 1) * 64;
    const int wn   = (wid >> 1) * 64;
    const int grp  = lane >> 2;
    const int tig  = lane & 3;

    const uint32_t* Arow = A + (size_t)(m0 + tid) * Cn;
    const uint32_t* Wrow = W + (size_t)(n0 + tid) * Cn;
    const uint32_t shb = (uint32_t)__cvta_generic_to_shared(smem);

    auto loadstage = [&](int it, int slot) {
        const uint32_t s0 = shb + slot * (2 * STG_W * 4);
        const uint32_t* as = Arow + it * 16;
        const uint32_t* ws = Wrow + it * 16;
#pragma unroll
        for (int c = 0; c < 4; c++) {
            cpa16(s0 + (tid * SST + c * 4) * 4, as + c * 4);
            cpa16(s0 + (STG_W + tid * SST + c * 4) * 4, ws + c * 4);
        }
    };

    float acc[4][8][4];
#pragma unroll
    for (int mt = 0; mt < 4; mt++)
#pragma unroll
        for (int nt = 0; nt < 8; nt++)
#pragma unroll
            for (int v = 0; v < 4; v++) acc[mt][nt][v] = 0.0f;

    loadstage(0, 0); CP_COMMIT();
    loadstage(1, 1); CP_COMMIT();

    for (int it = 0; it < 64; it++) {
        CP_WAIT1();
        __syncthreads();
        if (it + 2 < 64) loadstage(it + 2, (it + 2) % 3);
        CP_COMMIT();

        const uint32_t* As_ = smem + (it % 3) * 2 * STG_W;
        const uint32_t* Bs_ = As_ + STG_W;
#pragma unroll
        for (int ks = 0; ks < 2; ks++) {
            const int k0 = ks * 8;
            uint32_t af[4][4];
            uint32_t bf[8][2];
#pragma unroll
            for (int mt = 0; mt < 4; mt++) {
                const uint32_t* p = &As_[(wm + mt * 16 + grp) * SST + k0 + tig];
                af[mt][0] = p[0];
                af[mt][1] = p[8 * SST];
                af[mt][2] = p[4];
                af[mt][3] = p[8 * SST + 4];
            }
#pragma unroll
            for (int nt = 0; nt < 8; nt++) {
                const uint32_t* p = &Bs_[(wn + nt * 8 + grp) * SST + k0 + tig];
                bf[nt][0] = p[0];
                bf[nt][1] = p[4];
            }
#pragma unroll
            for (int mt = 0; mt < 4; mt++)
#pragma unroll
                for (int nt = 0; nt < 8; nt++)
                    mma_tf32(acc[mt][nt], af[mt], bf[nt][0], bf[nt][1]);
        }
    }

#pragma unroll
    for (int mt = 0; mt < 4; mt++) {
        const int r0 = m0 + wm + mt * 16 + grp;
#pragma unroll
        for (int nt = 0; nt < 8; nt++) {
            const int c0 = n0 + wn + nt * 8 + tig * 2;
#pragma unroll
            for (int v = 0; v < 4; v++) {
                const int gr = r0 + ((v >= 2) ? 8 : 0);
                const int gc = c0 + (v & 1);
                const float val = (acc[mt][nt][v] + bias[gc]) * scale;
                if (MODE == 0) {
                    const int b = gr / Tn, t = gr % Tn;
                    const int h = gc >> 6, d = gc & 63;
                    D[(((size_t)(b * Hn + h)) * Tn + t) * HDn + d] =
                        __uint_as_float(f2tf32(val));
                } else {
                    D[(size_t)gr * Cn + gc] = val;
                }
            }
        }
    }
}

// ---------------------------------------------------------------------------
// Tensor-core flash attention v2 (causal).
//   Inputs already tf32-rounded -> cp.async staging, no cvt.
//   Double-buffered K/V tiles (64 keys). Reversed q-tile order.
//   Layout (words): Qs/P [0,8704) stride 68 ; K bufs 8704 + buf*4352 ;
//                   V bufs 17408 + buf*4608 (stride 72).
// ---------------------------------------------------------------------------
#define SQP 68
#define SV  72
#define FL_K0 (128 * SQP)          // 8704
#define FL_V0 (FL_K0 + 2 * 64 * SQP)  // 17408
#define FLASH_SMEM ((FL_V0 + 2 * 64 * SV) * 4)  // 106496 bytes

__global__ __launch_bounds__(256)
void flash_tc2(const uint32_t* __restrict__ Qg, const uint32_t* __restrict__ Kg,
               const uint32_t* __restrict__ Vg, float* __restrict__ Ob)
{
    extern __shared__ uint32_t sh[];
    uint32_t* Qs = sh;

    const int bh  = blockIdx.y;
    const int qt  = (gridDim.x - 1) - blockIdx.x;   // heavy tiles first
    const int tid = threadIdx.x;
    const int lane = tid & 31;
    const int wid  = tid >> 5;
    const int grp  = lane >> 2;
    const int tig  = lane & 3;
    const int q0   = qt * 128;
    const int w0   = wid * 16;

    const uint32_t shb = (uint32_t)__cvta_generic_to_shared(sh);
    const uint32_t* Kbh = Kg + (size_t)bh * Tn * HDn;
    const uint32_t* Vbh = Vg + (size_t)bh * Tn * HDn;

    auto load_tile = [&](int kt, int buf) {
        const uint32_t* ks = Kbh + (size_t)kt * 64 * HDn;
        const uint32_t* vs = Vbh + (size_t)kt * 64 * HDn;
        const uint32_t kb = shb + (FL_K0 + buf * 64 * SQP) * 4;
        const uint32_t vb = shb + (FL_V0 + buf * 64 * SV) * 4;
#pragma unroll
        for (int j = 0; j < 4; j++) {
            const int c = tid + j * 256;     // 0..1023
            const int row = c >> 4, c4 = (c & 15) * 4;
            cpa16(kb + (row * SQP + c4) * 4, ks + row * 64 + c4);
            cpa16(vb + (row * SV + c4) * 4, vs + row * 64 + c4);
        }
    };

    const int nkt = 2 * qt + 2;
    load_tile(0, 0); CP_COMMIT();

    // stage Q (raw copy; already tf32)
    const uint32_t* qsrc = Qg + ((size_t)bh * Tn + q0) * HDn;
    for (int i = tid; i < 128 * 16; i += 256) {
        const int row = i >> 4, c4 = (i & 15) * 4;
        *(uint4*)&Qs[row * SQP + c4] = *(const uint4*)(qsrc + row * 64 + c4);
    }
    __syncthreads();

    uint32_t aq[8][4];
#pragma unroll
    for (int k = 0; k < 8; k++) {
        aq[k][0] = Qs[(w0 + grp) * SQP + k * 8 + tig];
        aq[k][1] = Qs[(w0 + grp + 8) * SQP + k * 8 + tig];
        aq[k][2] = Qs[(w0 + grp) * SQP + k * 8 + tig + 4];
        aq[k][3] = Qs[(w0 + grp + 8) * SQP + k * 8 + tig + 4];
    }
    __syncthreads();   // Qs now reusable as P

    float o[8][4];
#pragma unroll
    for (int n = 0; n < 8; n++)
#pragma unroll
        for (int v = 0; v < 4; v++) o[n][v] = 0.0f;
    float m0r = -1e30f, m1r = -1e30f, l0 = 0.0f, l1 = 0.0f;

    const int row0 = q0 + w0 + grp;
    const int row1 = row0 + 8;

    for (int kt = 0; kt < nkt; kt++) {
        __syncthreads();                       // buf (kt+1)&1 free for reload
        if (kt + 1 < nkt) load_tile(kt + 1, (kt + 1) & 1);
        CP_COMMIT();
        CP_WAIT1();
        __syncthreads();                       // tile kt visible to all

        const uint32_t* Ks = sh + FL_K0 + (kt & 1) * 64 * SQP;
        const uint32_t* Vs = sh + FL_V0 + (kt & 1) * 64 * SV;

        const int kb = kt * 64;
        const bool active = (kb <= q0 + w0 + 15);
        if (active) {
            float s[8][4];
#pragma unroll
            for (int n = 0; n < 8; n++)
#pragma unroll
                for (int v = 0; v < 4; v++) s[n][v] = 0.0f;
#pragma unroll
            for (int k = 0; k < 8; k++) {
#pragma unroll
                for (int n = 0; n < 8; n++) {
                    const uint32_t* kp = &Ks[(n * 8 + grp) * SQP + k * 8 + tig];
                    mma_tf32(s[n], aq[k], kp[0], kp[4]);
                }
            }

            if (kb + 63 > row0) {
#pragma unroll
                for (int n = 0; n < 8; n++) {
                    const int col = kb + n * 8 + tig * 2;
                    if (col > row0)     s[n][0] = -1e30f;
                    if (col + 1 > row0) s[n][1] = -1e30f;
                    if (col > row1)     s[n][2] = -1e30f;
                    if (col + 1 > row1) s[n][3] = -1e30f;
                }
            }

            float tm0 = -1e30f, tm1 = -1e30f;
#pragma unroll
            for (int n = 0; n < 8; n++) {
                tm0 = fmaxf(tm0, fmaxf(s[n][0], s[n][1]));
                tm1 = fmaxf(tm1, fmaxf(s[n][2], s[n][3]));
            }
            tm0 = fmaxf(tm0, __shfl_xor_sync(0xffffffff, tm0, 1));
            tm0 = fmaxf(tm0, __shfl_xor_sync(0xffffffff, tm0, 2));
            tm1 = fmaxf(tm1, __shfl_xor_sync(0xffffffff, tm1, 1));
            tm1 = fmaxf(tm1, __shfl_xor_sync(0xffffffff, tm1, 2));

            const float nm0 = fmaxf(m0r, tm0);
            const float nm1 = fmaxf(m1r, tm1);
            const float c0 = __expf(m0r - nm0);
            const float c1 = __expf(m1r - nm1);
            m0r = nm0; m1r = nm1;

            float ps0 = 0.0f, ps1 = 0.0f;
            uint32_t* p0row = &Qs[(w0 + grp) * SQP];
            uint32_t* p1row = &Qs[(w0 + grp + 8) * SQP];
#pragma unroll
            for (int n = 0; n < 8; n++) {
                const float e0 = __expf(s[n][0] - nm0);
                const float e1 = __expf(s[n][1] - nm0);
                const float e2 = __expf(s[n][2] - nm1);
                const float e3 = __expf(s[n][3] - nm1);
                ps0 += e0 + e1;
                ps1 += e2 + e3;
                const int c = n * 8 + tig * 2;
                p0row[c]     = f2tf32(e0);
                p0row[c + 1] = f2tf32(e1);
                p1row[c]     = f2tf32(e2);
                p1row[c + 1] = f2tf32(e3);
            }
            ps0 += __shfl_xor_sync(0xffffffff, ps0, 1);
            ps0 += __shfl_xor_sync(0xffffffff, ps0, 2);
            ps1 += __shfl_xor_sync(0xffffffff, ps1, 1);
            ps1 += __shfl_xor_sync(0xffffffff, ps1, 2);
            l0 = l0 * c0 + ps0;
            l1 = l1 * c1 + ps1;

#pragma unroll
            for (int n = 0; n < 8; n++) {
                o[n][0] *= c0; o[n][1] *= c0;
                o[n][2] *= c1; o[n][3] *= c1;
            }
            __syncwarp();

#pragma unroll
            for (int k = 0; k < 8; k++) {
                uint32_t ap[4];
                ap[0] = Qs[(w0 + grp) * SQP + k * 8 + tig];
                ap[1] = Qs[(w0 + grp + 8) * SQP + k * 8 + tig];
                ap[2] = Qs[(w0 + grp) * SQP + k * 8 + tig + 4];
                ap[3] = Qs[(w0 + grp + 8) * SQP + k * 8 + tig + 4];
#pragma unroll
                for (int n = 0; n < 8; n++) {
                    const uint32_t b0 = Vs[(k * 8 + tig) * SV + n * 8 + grp];
                    const uint32_t b1 = Vs[(k * 8 + tig + 4) * SV + n * 8 + grp];
                    mma_tf32(o[n], ap, b0, b1);
                }
            }
            __syncwarp();
        }
    }

    const float inv0 = 1.0f / l0;
    const float inv1 = 1.0f / l1;
    const int b = bh / Hn, h = bh % Hn;
    float* dst0 = Ob + ((size_t)(b * Tn) + row0) * Cn + h * HDn;
    float* dst1 = dst0 + (size_t)8 * Cn;
#pragma unroll
    for (int n = 0; n < 8; n++) {
        const int c = n * 8 + tig * 2;
        dst0[c]     = __uint_as_float(f2tf32(o[n][0] * inv0));
        dst0[c + 1] = __uint_as_float(f2tf32(o[n][1] * inv0));
        dst1[c]     = __uint_as_float(f2tf32(o[n][2] * inv1));
        dst1[c + 1] = __uint_as_float(f2tf32(o[n][3] * inv1));
    }
}

// ---------------------------------------------------------------------------
extern "C" void kernel_launch(void* const* d_in, const int* in_sizes, int n_in,
                              void* d_out, int out_size)
{
    const float* x  = (const float*)d_in[0];
    const float* Wq = (const float*)d_in[1];
    const float* bq = (const float*)d_in[2];
    const float* Wk = (const float*)d_in[3];
    const float* bk = (const float*)d_in[4];
    const float* Wv = (const float*)d_in[5];
    const float* bv = (const float*)d_in[6];
    const float* Wp = (const float*)d_in[7];
    const float* bp = (const float*)d_in[8];
    float* out = (float*)d_out;

    float *pq, *pk, *pv, *pa;
    uint32_t *pxt, *pwq, *pwk, *pwv, *pwp;
    cudaGetSymbolAddress((void**)&pq, g_q);
    cudaGetSymbolAddress((void**)&pk, g_k);
    cudaGetSymbolAddress((void**)&pv, g_v);
    cudaGetSymbolAddress((void**)&pa, g_a);
    cudaGetSymbolAddress((void**)&pxt, g_xt);
    cudaGetSymbolAddress((void**)&pwq, g_wqt);
    cudaGetSymbolAddress((void**)&pwk, g_wkt);
    cudaGetSymbolAddress((void**)&pwv, g_wvt);
    cudaGetSymbolAddress((void**)&pwp, g_wpt);

    cudaFuncSetAttribute(tf32_gemm2<0>,
        cudaFuncAttributeMaxDynamicSharedMemorySize, GEMM_SMEM);
    cudaFuncSetAttribute(tf32_gemm2<1>,
        cudaFuncAttributeMaxDynamicSharedMemorySize, GEMM_SMEM);
    cudaFuncSetAttribute(flash_tc2,
        cudaFuncAttributeMaxDynamicSharedMemorySize, FLASH_SMEM);

    prep_cvt<<<8192, 256>>>((const float4*)x,
                            (const float4*)Wq, (const float4*)Wk,
                            (const float4*)Wv, (const float4*)Wp,
                            (uint4*)pxt, (uint4*)pwq, (uint4*)pwk,
                            (uint4*)pwv, (uint4*)pwp);

    dim3 gg(Cn / 128, Mrows / 128);   // (8, 32)
    const float qscale = 1.0f / 8.0f;

    tf32_gemm2<0><<<gg, 128, GEMM_SMEM>>>(pxt, pwq, bq, pq, qscale);
    tf32_gemm2<0><<<gg, 128, GEMM_SMEM>>>(pxt, pwk, bk, pk, 1.0f);
    tf32_gemm2<0><<<gg, 128, GEMM_SMEM>>>(pxt, pwv, bv, pv, 1.0f);

    dim3 fg(Tn / 128, Bn * Hn);       // (16, 32)
    flash_tc2<<<fg, 256, FLASH_SMEM>>>((const uint32_t*)pq, (const uint32_t*)pk,
                                       (const uint32_t*)pv, pa);

    tf32_gemm2<1><<<gg, 128, GEMM_SMEM>>>((const uint32_t*)pa, pwp, bp, out, 1.0f);
}

// round 5
// speedup vs baseline: 1.1686x; 1.1686x over previous
#include <cuda_runtime.h>
#include <stdint.h>

// Problem dims
#define Bn 2
#define Tn 2048
#define Cn 1024
#define Hn 16
#define HDn 64
#define Mrows (Bn * Tn)   // 4096

// Scratch (allocation-free: __device__ globals)
__device__ float g_q[Bn * Hn * Tn * HDn];   // tf32-rounded, pre-scaled by 1/8
__device__ float g_k[Bn * Hn * Tn * HDn];   // tf32-rounded
__device__ float g_v[Bn * Hn * Tn * HDn];   // tf32-rounded
__device__ float g_a[Bn * Tn * Cn];         // flash out, tf32-rounded
__device__ uint32_t g_xt[Mrows * Cn];       // x  pre-rounded to tf32
__device__ uint32_t g_wqt[Cn * Cn];
__device__ uint32_t g_wkt[Cn * Cn];
__device__ uint32_t g_wvt[Cn * Cn];
__device__ uint32_t g_wpt[Cn * Cn];

__device__ __forceinline__ uint32_t f2tf32(float x) {
    uint32_t y;
    asm("cvt.rna.tf32.f32 %0, %1;" : "=r"(y) : "f"(x));
    return y;
}

__device__ __forceinline__ void mma_tf32(float* c, const uint32_t* a,
                                         uint32_t b0, uint32_t b1) {
    asm volatile(
        "mma.sync.aligned.m16n8k8.row.col.f32.tf32.tf32.f32 "
        "{%0,%1,%2,%3}, {%4,%5,%6,%7}, {%8,%9}, {%0,%1,%2,%3};"
        : "+f"(c[0]), "+f"(c[1]), "+f"(c[2]), "+f"(c[3])
        : "r"(a[0]), "r"(a[1]), "r"(a[2]), "r"(a[3]), "r"(b0), "r"(b1));
}

__device__ __forceinline__ void cpa16(uint32_t dst, const void* src) {
    asm volatile("cp.async.ca.shared.global [%0], [%1], 16;" :: "r"(dst), "l"(src));
}
#define CP_COMMIT() asm volatile("cp.async.commit_group;")
#define CP_WAIT1()  asm volatile("cp.async.wait_group 1;")

// ---------------------------------------------------------------------------
// prep: round x and the 4 weights to tf32 once (vectorized).
// ---------------------------------------------------------------------------
__global__ __launch_bounds__(256)
void prep_cvt(const float4* __restrict__ x,
              const float4* __restrict__ wq, const float4* __restrict__ wk,
              const float4* __restrict__ wv, const float4* __restrict__ wp,
              uint4* __restrict__ xt,
              uint4* __restrict__ wqt, uint4* __restrict__ wkt,
              uint4* __restrict__ wvt, uint4* __restrict__ wpt)
{
    const int i = blockIdx.x * 256 + threadIdx.x;   // 0 .. 2M-1
    const float4* src; uint4* dst; int off;
    if (i < (1 << 20))            { src = x;  dst = xt;  off = i; }
    else if (i < (1 << 20) + (1 << 18))     { src = wq; dst = wqt; off = i - (1 << 20); }
    else if (i < (1 << 20) + 2 * (1 << 18)) { src = wk; dst = wkt; off = i - (1 << 20) - (1 << 18); }
    else if (i < (1 << 20) + 3 * (1 << 18)) { src = wv; dst = wvt; off = i - (1 << 20) - 2 * (1 << 18); }
    else                                    { src = wp; dst = wpt; off = i - (1 << 20) - 3 * (1 << 18); }
    float4 v = src[off];
    uint4 u = {f2tf32(v.x), f2tf32(v.y), f2tf32(v.z), f2tf32(v.w)};
    dst[off] = u;
}

// ---------------------------------------------------------------------------
// tf32 GEMM v3: D = (A @ W^T + bias) * scale ; inputs pre-rounded to tf32.
//   256 threads (8 warps), block 128x128, warp tile 64x32 (R3's proven shape),
//   BK=16, 3-stage cp.async pipeline, no in-loop cvt.
//   MODE 0: z in {0,1,2} selects Wq/Wk/Wv -> scatter into [B,H,T,64] (tf32
//           rounded output; z==0 scaled by 1/8).
//   MODE 1: plain row-major fp32 output.
// ---------------------------------------------------------------------------
#define SST 20
#define STG_W (128 * SST)               // 2560 words per tensor per stage
#define GEMM_SMEM (3 * 2 * STG_W * 4)   // 61440 bytes

template <int MODE>
__global__ __launch_bounds__(256)
void tf32_gemm3(const uint32_t* __restrict__ A,
                const uint32_t* __restrict__ W0, const uint32_t* __restrict__ W1,
                const uint32_t* __restrict__ W2,
                const float* __restrict__ b0p, const float* __restrict__ b1p,
                const float* __restrict__ b2p,
                float* __restrict__ D0, float* __restrict__ D1,
                float* __restrict__ D2)
{
    extern __shared__ uint32_t smem[];
    const int z = blockIdx.z;
    const uint32_t* W = (z == 0) ? W0 : ((z == 1) ? W1 : W2);
    const float* bias = (z == 0) ? b0p : ((z == 1) ? b1p : b2p);
    float* D = (z == 0) ? D0 : ((z == 1) ? D1 : D2);
    const float scale = (MODE == 0 && z == 0) ? 0.125f : 1.0f;

    const int tid  = threadIdx.x;
    const int lane = tid & 31;
    const int wid  = tid >> 5;             // 0..7
    const int m0   = blockIdx.y * 128;
    const int n0   = blockIdx.x * 128;
    const int wm   = (wid & 1) * 64;
    const int wn   = (wid >> 1) * 32;
    const int grp  = lane >> 2;
    const int tig  = lane & 3;

    // global->smem mapping: 2 float4 per tensor per thread
    const int lr = tid >> 1;               // 0..127
    const int lc = (tid & 1) * 8;          // 0 or 8
    const uint32_t* Ag = A + (size_t)(m0 + lr) * Cn + lc;
    const uint32_t* Wg = W + (size_t)(n0 + lr) * Cn + lc;
    const uint32_t shb = (uint32_t)__cvta_generic_to_shared(smem);

    auto loadstage = [&](int it, int slot) {
        const uint32_t s0 = shb + slot * (2 * STG_W * 4);
        const uint32_t dofs = (lr * SST + lc) * 4;
        const uint32_t* as = Ag + it * 16;
        const uint32_t* ws = Wg + it * 16;
        cpa16(s0 + dofs, as);
        cpa16(s0 + dofs + 16, as + 4);
        cpa16(s0 + STG_W * 4 + dofs, ws);
        cpa16(s0 + STG_W * 4 + dofs + 16, ws + 4);
    };

    float acc[4][4][4];
#pragma unroll
    for (int i = 0; i < 4; i++)
#pragma unroll
        for (int j = 0; j < 4; j++)
#pragma unroll
            for (int v = 0; v < 4; v++) acc[i][j][v] = 0.0f;

    loadstage(0, 0); CP_COMMIT();
    loadstage(1, 1); CP_COMMIT();

    for (int it = 0; it < 64; it++) {
        CP_WAIT1();
        __syncthreads();
        if (it + 2 < 64) loadstage(it + 2, (it + 2) % 3);
        CP_COMMIT();

        const uint32_t* As_ = smem + (it % 3) * 2 * STG_W;
        const uint32_t* Bs_ = As_ + STG_W;
#pragma unroll
        for (int ks = 0; ks < 2; ks++) {
            const int k0 = ks * 8;
            uint32_t af[4][4];
            uint32_t bf[4][2];
#pragma unroll
            for (int mt = 0; mt < 4; mt++) {
                const uint32_t* p = &As_[(wm + mt * 16 + grp) * SST + k0 + tig];
                af[mt][0] = p[0];
                af[mt][1] = p[8 * SST];
                af[mt][2] = p[4];
                af[mt][3] = p[8 * SST + 4];
            }
#pragma unroll
            for (int nt = 0; nt < 4; nt++) {
                const uint32_t* p = &Bs_[(wn + nt * 8 + grp) * SST + k0 + tig];
                bf[nt][0] = p[0];
                bf[nt][1] = p[4];
            }
#pragma unroll
            for (int mt = 0; mt < 4; mt++)
#pragma unroll
                for (int nt = 0; nt < 4; nt++)
                    mma_tf32(acc[mt][nt], af[mt], bf[nt][0], bf[nt][1]);
        }
    }

#pragma unroll
    for (int mt = 0; mt < 4; mt++) {
        const int r0 = m0 + wm + mt * 16 + grp;
#pragma unroll
        for (int nt = 0; nt < 4; nt++) {
            const int c0 = n0 + wn + nt * 8 + tig * 2;
#pragma unroll
            for (int v = 0; v < 4; v++) {
                const int gr = r0 + ((v >= 2) ? 8 : 0);
                const int gc = c0 + (v & 1);
                const float val = (acc[mt][nt][v] + bias[gc]) * scale;
                if (MODE == 0) {
                    const int b = gr / Tn, t = gr % Tn;
                    const int h = gc >> 6, d = gc & 63;
                    D[(((size_t)(b * Hn + h)) * Tn + t) * HDn + d] =
                        __uint_as_float(f2tf32(val));
                } else {
                    D[(size_t)gr * Cn + gc] = val;
                }
            }
        }
    }
}

// ---------------------------------------------------------------------------
// Tensor-core flash attention v2 (causal) — unchanged from R4 (validated).
// ---------------------------------------------------------------------------
#define SQP 68
#define SV  72
#define FL_K0 (128 * SQP)
#define FL_V0 (FL_K0 + 2 * 64 * SQP)
#define FLASH_SMEM ((FL_V0 + 2 * 64 * SV) * 4)  // 106496 bytes

__global__ __launch_bounds__(256)
void flash_tc2(const uint32_t* __restrict__ Qg, const uint32_t* __restrict__ Kg,
               const uint32_t* __restrict__ Vg, float* __restrict__ Ob)
{
    extern __shared__ uint32_t sh[];
    uint32_t* Qs = sh;

    const int bh  = blockIdx.y;
    const int qt  = (gridDim.x - 1) - blockIdx.x;   // heavy tiles first
    const int tid = threadIdx.x;
    const int lane = tid & 31;
    const int wid  = tid >> 5;
    const int grp  = lane >> 2;
    const int tig  = lane & 3;
    const int q0   = qt * 128;
    const int w0   = wid * 16;

    const uint32_t shb = (uint32_t)__cvta_generic_to_shared(sh);
    const uint32_t* Kbh = Kg + (size_t)bh * Tn * HDn;
    const uint32_t* Vbh = Vg + (size_t)bh * Tn * HDn;

    auto load_tile = [&](int kt, int buf) {
        const uint32_t* ks = Kbh + (size_t)kt * 64 * HDn;
        const uint32_t* vs = Vbh + (size_t)kt * 64 * HDn;
        const uint32_t kb = shb + (FL_K0 + buf * 64 * SQP) * 4;
        const uint32_t vb = shb + (FL_V0 + buf * 64 * SV) * 4;
#pragma unroll
        for (int j = 0; j < 4; j++) {
            const int c = tid + j * 256;
            const int row = c >> 4, c4 = (c & 15) * 4;
            cpa16(kb + (row * SQP + c4) * 4, ks + row * 64 + c4);
            cpa16(vb + (row * SV + c4) * 4, vs + row * 64 + c4);
        }
    };

    const int nkt = 2 * qt + 2;
    load_tile(0, 0); CP_COMMIT();

    const uint32_t* qsrc = Qg + ((size_t)bh * Tn + q0) * HDn;
    for (int i = tid; i < 128 * 16; i += 256) {
        const int row = i >> 4, c4 = (i & 15) * 4;
        *(uint4*)&Qs[row * SQP + c4] = *(const uint4*)(qsrc + row * 64 + c4);
    }
    __syncthreads();

    uint32_t aq[8][4];
#pragma unroll
    for (int k = 0; k < 8; k++) {
        aq[k][0] = Qs[(w0 + grp) * SQP + k * 8 + tig];
        aq[k][1] = Qs[(w0 + grp + 8) * SQP + k * 8 + tig];
        aq[k][2] = Qs[(w0 + grp) * SQP + k * 8 + tig + 4];
        aq[k][3] = Qs[(w0 + grp + 8) * SQP + k * 8 + tig + 4];
    }
    __syncthreads();

    float o[8][4];
#pragma unroll
    for (int n = 0; n < 8; n++)
#pragma unroll
        for (int v = 0; v < 4; v++) o[n][v] = 0.0f;
    float m0r = -1e30f, m1r = -1e30f, l0 = 0.0f, l1 = 0.0f;

    const int row0 = q0 + w0 + grp;
    const int row1 = row0 + 8;

    for (int kt = 0; kt < nkt; kt++) {
        __syncthreads();
        if (kt + 1 < nkt) load_tile(kt + 1, (kt + 1) & 1);
        CP_COMMIT();
        CP_WAIT1();
        __syncthreads();

        const uint32_t* Ks = sh + FL_K0 + (kt & 1) * 64 * SQP;
        const uint32_t* Vs = sh + FL_V0 + (kt & 1) * 64 * SV;

        const int kb = kt * 64;
        const bool active = (kb <= q0 + w0 + 15);
        if (active) {
            float s[8][4];
#pragma unroll
            for (int n = 0; n < 8; n++)
#pragma unroll
                for (int v = 0; v < 4; v++) s[n][v] = 0.0f;
#pragma unroll
            for (int k = 0; k < 8; k++) {
#pragma unroll
                for (int n = 0; n < 8; n++) {
                    const uint32_t* kp = &Ks[(n * 8 + grp) * SQP + k * 8 + tig];
                    mma_tf32(s[n], aq[k], kp[0], kp[4]);
                }
            }

            if (kb + 63 > row0) {
#pragma unroll
                for (int n = 0; n < 8; n++) {
                    const int col = kb + n * 8 + tig * 2;
                    if (col > row0)     s[n][0] = -1e30f;
                    if (col + 1 > row0) s[n][1] = -1e30f;
                    if (col > row1)     s[n][2] = -1e30f;
                    if (col + 1 > row1) s[n][3] = -1e30f;
                }
            }

            float tm0 = -1e30f, tm1 = -1e30f;
#pragma unroll
            for (int n = 0; n < 8; n++) {
                tm0 = fmaxf(tm0, fmaxf(s[n][0], s[n][1]));
                tm1 = fmaxf(tm1, fmaxf(s[n][2], s[n][3]));
            }
            tm0 = fmaxf(tm0, __shfl_xor_sync(0xffffffff, tm0, 1));
            tm0 = fmaxf(tm0, __shfl_xor_sync(0xffffffff, tm0, 2));
            tm1 = fmaxf(tm1, __shfl_xor_sync(0xffffffff, tm1, 1));
            tm1 = fmaxf(tm1, __shfl_xor_sync(0xffffffff, tm1, 2));

            const float nm0 = fmaxf(m0r, tm0);
            const float nm1 = fmaxf(m1r, tm1);
            const float c0 = __expf(m0r - nm0);
            const float c1 = __expf(m1r - nm1);
            m0r = nm0; m1r = nm1;

            float ps0 = 0.0f, ps1 = 0.0f;
            uint32_t* p0row = &Qs[(w0 + grp) * SQP];
            uint32_t* p1row = &Qs[(w0 + grp + 8) * SQP];
#pragma unroll
            for (int n = 0; n < 8; n++) {
                const float e0 = __expf(s[n][0] - nm0);
                const float e1 = __expf(s[n][1] - nm0);
                const float e2 = __expf(s[n][2] - nm1);
                const float e3 = __expf(s[n][3] - nm1);
                ps0 += e0 + e1;
                ps1 += e2 + e3;
                const int c = n * 8 + tig * 2;
                p0row[c]     = f2tf32(e0);
                p0row[c + 1] = f2tf32(e1);
                p1row[c]     = f2tf32(e2);
                p1row[c + 1] = f2tf32(e3);
            }
            ps0 += __shfl_xor_sync(0xffffffff, ps0, 1);
            ps0 += __shfl_xor_sync(0xffffffff, ps0, 2);
            ps1 += __shfl_xor_sync(0xffffffff, ps1, 1);
            ps1 += __shfl_xor_sync(0xffffffff, ps1, 2);
            l0 = l0 * c0 + ps0;
            l1 = l1 * c1 + ps1;

#pragma unroll
            for (int n = 0; n < 8; n++) {
                o[n][0] *= c0; o[n][1] *= c0;
                o[n][2] *= c1; o[n][3] *= c1;
            }
            __syncwarp();

#pragma unroll
            for (int k = 0; k < 8; k++) {
                uint32_t ap[4];
                ap[0] = Qs[(w0 + grp) * SQP + k * 8 + tig];
                ap[1] = Qs[(w0 + grp + 8) * SQP + k * 8 + tig];
                ap[2] = Qs[(w0 + grp) * SQP + k * 8 + tig + 4];
                ap[3] = Qs[(w0 + grp + 8) * SQP + k * 8 + tig + 4];
#pragma unroll
                for (int n = 0; n < 8; n++) {
                    const uint32_t b0 = Vs[(k * 8 + tig) * SV + n * 8 + grp];
                    const uint32_t b1 = Vs[(k * 8 + tig + 4) * SV + n * 8 + grp];
                    mma_tf32(o[n], ap, b0, b1);
                }
            }
            __syncwarp();
        }
    }

    const float inv0 = 1.0f / l0;
    const float inv1 = 1.0f / l1;
    const int b = bh / Hn, h = bh % Hn;
    float* dst0 = Ob + ((size_t)(b * Tn) + row0) * Cn + h * HDn;
    float* dst1 = dst0 + (size_t)8 * Cn;
#pragma unroll
    for (int n = 0; n < 8; n++) {
        const int c = n * 8 + tig * 2;
        dst0[c]     = __uint_as_float(f2tf32(o[n][0] * inv0));
        dst0[c + 1] = __uint_as_float(f2tf32(o[n][1] * inv0));
        dst1[c]     = __uint_as_float(f2tf32(o[n][2] * inv1));
        dst1[c + 1] = __uint_as_float(f2tf32(o[n][3] * inv1));
    }
}

// ---------------------------------------------------------------------------
extern "C" void kernel_launch(void* const* d_in, const int* in_sizes, int n_in,
                              void* d_out, int out_size)
{
    const float* x  = (const float*)d_in[0];
    const float* Wq = (const float*)d_in[1];
    const float* bq = (const float*)d_in[2];
    const float* Wk = (const float*)d_in[3];
    const float* bk = (const float*)d_in[4];
    const float* Wv = (const float*)d_in[5];
    const float* bv = (const float*)d_in[6];
    const float* Wp = (const float*)d_in[7];
    const float* bp = (const float*)d_in[8];
    float* out = (float*)d_out;

    float *pq, *pk, *pv, *pa;
    uint32_t *pxt, *pwq, *pwk, *pwv, *pwp;
    cudaGetSymbolAddress((void**)&pq, g_q);
    cudaGetSymbolAddress((void**)&pk, g_k);
    cudaGetSymbolAddress((void**)&pv, g_v);
    cudaGetSymbolAddress((void**)&pa, g_a);
    cudaGetSymbolAddress((void**)&pxt, g_xt);
    cudaGetSymbolAddress((void**)&pwq, g_wqt);
    cudaGetSymbolAddress((void**)&pwk, g_wkt);
    cudaGetSymbolAddress((void**)&pwv, g_wvt);
    cudaGetSymbolAddress((void**)&pwp, g_wpt);

    cudaFuncSetAttribute(tf32_gemm3<0>,
        cudaFuncAttributeMaxDynamicSharedMemorySize, GEMM_SMEM);
    cudaFuncSetAttribute(tf32_gemm3<1>,
        cudaFuncAttributeMaxDynamicSharedMemorySize, GEMM_SMEM);
    cudaFuncSetAttribute(flash_tc2,
        cudaFuncAttributeMaxDynamicSharedMemorySize, FLASH_SMEM);

    prep_cvt<<<8192, 256>>>((const float4*)x,
                            (const float4*)Wq, (const float4*)Wk,
                            (const float4*)Wv, (const float4*)Wp,
                            (uint4*)pxt, (uint4*)pwq, (uint4*)pwk,
                            (uint4*)pwv, (uint4*)pwp);

    // Fused QKV: gridDim.z selects the weight/bias/output triple
    dim3 gq(Cn / 128, Mrows / 128, 3);   // (8, 32, 3)
    tf32_gemm3<0><<<gq, 256, GEMM_SMEM>>>(pxt, pwq, pwk, pwv,
                                          bq, bk, bv, pq, pk, pv);

    dim3 fg(Tn / 128, Bn * Hn);          // (16, 32)
    flash_tc2<<<fg, 256, FLASH_SMEM>>>((const uint32_t*)pq, (const uint32_t*)pk,
                                       (const uint32_t*)pv, pa);

    dim3 gp(Cn / 128, Mrows / 128, 1);   // (8, 32, 1)
    tf32_gemm3<1><<<gp, 256, GEMM_SMEM>>>((const uint32_t*)pa, pwp, pwp, pwp,
                                          bp, bp, bp, out, out, out);
}

// round 6
// speedup vs baseline: 1.2140x; 1.0389x over previous
#include <cuda_runtime.h>
#include <stdint.h>

// Problem dims
#define Bn 2
#define Tn 2048
#define Cn 1024
#define Hn 16
#define HDn 64
#define Mrows (Bn * Tn)   // 4096

// Scratch (allocation-free: __device__ globals)
__device__ float g_q[Bn * Hn * Tn * HDn];   // tf32-rounded, pre-scaled by 1/8
__device__ float g_k[Bn * Hn * Tn * HDn];   // tf32-rounded
__device__ float g_v[Bn * Hn * Tn * HDn];   // tf32-rounded
__device__ float g_a[Bn * Tn * Cn];         // flash out, tf32, k-permuted blocks
__device__ uint32_t g_xt[Mrows * Cn];       // x  tf32, k-permuted 16-blocks
__device__ uint32_t g_wqt[Cn * Cn];         // weights tf32, k-permuted
__device__ uint32_t g_wkt[Cn * Cn];
__device__ uint32_t g_wvt[Cn * Cn];
__device__ uint32_t g_wpt[Cn * Cn];

__device__ __forceinline__ uint32_t f2tf32(float x) {
    uint32_t y;
    asm("cvt.rna.tf32.f32 %0, %1;" : "=r"(y) : "f"(x));
    return y;
}

__device__ __forceinline__ void mma_tf32(float* c, const uint32_t* a,
                                         uint32_t b0, uint32_t b1) {
    asm volatile(
        "mma.sync.aligned.m16n8k8.row.col.f32.tf32.tf32.f32 "
        "{%0,%1,%2,%3}, {%4,%5,%6,%7}, {%8,%9}, {%0,%1,%2,%3};"
        : "+f"(c[0]), "+f"(c[1]), "+f"(c[2]), "+f"(c[3])
        : "r"(a[0]), "r"(a[1]), "r"(a[2]), "r"(a[3]), "r"(b0), "r"(b1));
}

__device__ __forceinline__ void cpa16(uint32_t dst, const void* src) {
    asm volatile("cp.async.ca.shared.global [%0], [%1], 16;" :: "r"(dst), "l"(src));
}
#define CP_COMMIT() asm volatile("cp.async.commit_group;")
#define CP_WAIT1()  asm volatile("cp.async.wait_group 1;")

// ---------------------------------------------------------------------------
// prep: tf32-round AND k-permute each 16-float block:
//   out[j] = tf32(in[(j%4)*4 + j/4])  (4x4 transpose within block)
// so a fragment thread's k-set {tig, tig+4, tig+8, tig+12} is contiguous.
// One thread per 16-float block. x: 2^18 blocks; each W: 2^16 blocks.
// ---------------------------------------------------------------------------
__global__ __launch_bounds__(256)
void prep_cvt(const float* __restrict__ x,
              const float* __restrict__ wq, const float* __restrict__ wk,
              const float* __restrict__ wv, const float* __restrict__ wp,
              uint32_t* __restrict__ xt,
              uint32_t* __restrict__ wqt, uint32_t* __restrict__ wkt,
              uint32_t* __restrict__ wvt, uint32_t* __restrict__ wpt)
{
    const int i = blockIdx.x * 256 + threadIdx.x;   // 0 .. 2^19-1
    const float* src; uint32_t* dst; int off;
    if (i < (1 << 18)) { src = x; dst = xt; off = i; }
    else {
        const int j = i - (1 << 18);
        const int w = j >> 16;
        off = j & 65535;
        src = (w == 0) ? wq : (w == 1) ? wk : (w == 2) ? wv : wp;
        dst = (w == 0) ? wqt : (w == 1) ? wkt : (w == 2) ? wvt : wpt;
    }
    const float4* s = (const float4*)src + (size_t)off * 4;
    float4 v0 = s[0], v1 = s[1], v2 = s[2], v3 = s[3];
    uint4* d = (uint4*)dst + (size_t)off * 4;
    uint4 u0 = {f2tf32(v0.x), f2tf32(v1.x), f2tf32(v2.x), f2tf32(v3.x)};
    uint4 u1 = {f2tf32(v0.y), f2tf32(v1.y), f2tf32(v2.y), f2tf32(v3.y)};
    uint4 u2 = {f2tf32(v0.z), f2tf32(v1.z), f2tf32(v2.z), f2tf32(v3.z)};
    uint4 u3 = {f2tf32(v0.w), f2tf32(v1.w), f2tf32(v2.w), f2tf32(v3.w)};
    d[0] = u0; d[1] = u1; d[2] = u2; d[3] = u3;
}

// ---------------------------------------------------------------------------
// tf32 GEMM v4: D = (A @ W^T + bias) * scale ; inputs tf32 + k-permuted.
//   256 thr (8 warps), block 128x128, warp tile 64x32, BK=16, 3-stage cp.async.
//   Smem stage: row stride 16 words (no pad), chunk XOR-swizzled on (row&3).
//   Fragment loads: LDS.128, bank-conflict-free, one load covers both ks.
// ---------------------------------------------------------------------------
#define STG_W 2048                       // words per tensor per stage (128*16)
#define GEMM_SMEM (3 * 2 * STG_W * 4)    // 49152 bytes

template <int MODE>
__global__ __launch_bounds__(256, 2)
void tf32_gemm4(const uint32_t* __restrict__ A,
                const uint32_t* __restrict__ W0, const uint32_t* __restrict__ W1,
                const uint32_t* __restrict__ W2,
                const float* __restrict__ b0p, const float* __restrict__ b1p,
                const float* __restrict__ b2p,
                float* __restrict__ D0, float* __restrict__ D1,
                float* __restrict__ D2)
{
    extern __shared__ uint32_t smem[];
    const int z = blockIdx.z;
    const uint32_t* W = (z == 0) ? W0 : ((z == 1) ? W1 : W2);
    const float* bias = (z == 0) ? b0p : ((z == 1) ? b1p : b2p);
    float* D = (z == 0) ? D0 : ((z == 1) ? D1 : D2);
    const float scale = (MODE == 0 && z == 0) ? 0.125f : 1.0f;

    const int tid  = threadIdx.x;
    const int lane = tid & 31;
    const int wid  = tid >> 5;
    const int m0   = blockIdx.y * 128;
    const int n0   = blockIdx.x * 128;
    const int wm   = (wid & 1) * 64;
    const int wn   = (wid >> 1) * 32;
    const int grp  = lane >> 2;
    const int tig  = lane & 3;

    // global->smem: thread writes 2 chunks (16B) of one row per tensor
    const int lr = tid >> 1;               // 0..127
    const int c0 = (tid & 1) * 2;          // chunk 0/1 or 2/3
    const uint32_t* Ag = A + (size_t)(m0 + lr) * Cn + c0 * 4;
    const uint32_t* Wg = W + (size_t)(n0 + lr) * Cn + c0 * 4;
    const uint32_t shb = (uint32_t)__cvta_generic_to_shared(smem);
    const uint32_t sw  = lr & 3;
    const uint32_t dA0 = (lr * 16 + ((c0 + 0) ^ sw) * 4) * 4;
    const uint32_t dA1 = (lr * 16 + ((c0 + 1) ^ sw) * 4) * 4;

    auto loadstage = [&](int it, int slot) {
        const uint32_t s0 = shb + slot * (2 * STG_W * 4);
        const uint32_t* as = Ag + it * 16;
        const uint32_t* ws = Wg + it * 16;
        cpa16(s0 + dA0, as);
        cpa16(s0 + dA1, as + 4);
        cpa16(s0 + STG_W * 4 + dA0, ws);
        cpa16(s0 + STG_W * 4 + dA1, ws + 4);
    };

    float acc[4][4][4];
#pragma unroll
    for (int i = 0; i < 4; i++)
#pragma unroll
        for (int j = 0; j < 4; j++)
#pragma unroll
            for (int v = 0; v < 4; v++) acc[i][j][v] = 0.0f;

    loadstage(0, 0); CP_COMMIT();
    loadstage(1, 1); CP_COMMIT();

    const int csel = (tig ^ (grp & 3)) * 4;   // swizzled chunk offset (words)

    for (int it = 0; it < 64; it++) {
        CP_WAIT1();
        __syncthreads();
        if (it + 2 < 64) loadstage(it + 2, (it + 2) % 3);
        CP_COMMIT();

        const uint32_t* As_ = smem + (it % 3) * 2 * STG_W;
        const uint32_t* Bs_ = As_ + STG_W;

        uint4 aA[4][2];
        uint4 bB[4];
#pragma unroll
        for (int mt = 0; mt < 4; mt++) {
            const int r = wm + mt * 16 + grp;
            aA[mt][0] = *(const uint4*)&As_[r * 16 + csel];
            aA[mt][1] = *(const uint4*)&As_[(r + 8) * 16 + csel];
        }
#pragma unroll
        for (int nt = 0; nt < 4; nt++) {
            const int r = wn + nt * 8 + grp;
            bB[nt] = *(const uint4*)&Bs_[r * 16 + csel];
        }

#pragma unroll
        for (int ks = 0; ks < 2; ks++) {
#pragma unroll
            for (int mt = 0; mt < 4; mt++) {
                uint32_t af[4];
                if (ks == 0) {
                    af[0] = aA[mt][0].x; af[1] = aA[mt][1].x;
                    af[2] = aA[mt][0].y; af[3] = aA[mt][1].y;
                } else {
                    af[0] = aA[mt][0].z; af[1] = aA[mt][1].z;
                    af[2] = aA[mt][0].w; af[3] = aA[mt][1].w;
                }
#pragma unroll
                for (int nt = 0; nt < 4; nt++) {
                    const uint32_t b0 = (ks == 0) ? bB[nt].x : bB[nt].z;
                    const uint32_t b1 = (ks == 0) ? bB[nt].y : bB[nt].w;
                    mma_tf32(acc[mt][nt], af, b0, b1);
                }
            }
        }
    }

#pragma unroll
    for (int mt = 0; mt < 4; mt++) {
        const int r0 = m0 + wm + mt * 16 + grp;
#pragma unroll
        for (int nt = 0; nt < 4; nt++) {
            const int c0_ = n0 + wn + nt * 8 + tig * 2;
#pragma unroll
            for (int v = 0; v < 4; v++) {
                const int gr = r0 + ((v >= 2) ? 8 : 0);
                const int gc = c0_ + (v & 1);
                const float val = (acc[mt][nt][v] + bias[gc]) * scale;
                if (MODE == 0) {
                    const int b = gr / Tn, t = gr % Tn;
                    const int h = gc >> 6, d = gc & 63;
                    D[(((size_t)(b * Hn + h)) * Tn + t) * HDn + d] =
                        __uint_as_float(f2tf32(val));
                } else {
                    D[(size_t)gr * Cn + gc] = val;
                }
            }
        }
    }
}

// ---------------------------------------------------------------------------
// Tensor-core flash attention v2 (causal) — compute unchanged (validated).
// Epilogue writes g_a with the k-permuted 16-block layout for the proj GEMM.
// ---------------------------------------------------------------------------
#define SQP 68
#define SV  72
#define FL_K0 (128 * SQP)
#define FL_V0 (FL_K0 + 2 * 64 * SQP)
#define FLASH_SMEM ((FL_V0 + 2 * 64 * SV) * 4)  // 106496 bytes

__global__ __launch_bounds__(256)
void flash_tc2(const uint32_t* __restrict__ Qg, const uint32_t* __restrict__ Kg,
               const uint32_t* __restrict__ Vg, float* __restrict__ Ob)
{
    extern __shared__ uint32_t sh[];
    uint32_t* Qs = sh;

    const int bh  = blockIdx.y;
    const int qt  = (gridDim.x - 1) - blockIdx.x;   // heavy tiles first
    const int tid = threadIdx.x;
    const int lane = tid & 31;
    const int wid  = tid >> 5;
    const int grp  = lane >> 2;
    const int tig  = lane & 3;
    const int q0   = qt * 128;
    const int w0   = wid * 16;

    const uint32_t shb = (uint32_t)__cvta_generic_to_shared(sh);
    const uint32_t* Kbh = Kg + (size_t)bh * Tn * HDn;
    const uint32_t* Vbh = Vg + (size_t)bh * Tn * HDn;

    auto load_tile = [&](int kt, int buf) {
        const uint32_t* ks = Kbh + (size_t)kt * 64 * HDn;
        const uint32_t* vs = Vbh + (size_t)kt * 64 * HDn;
        const uint32_t kb = shb + (FL_K0 + buf * 64 * SQP) * 4;
        const uint32_t vb = shb + (FL_V0 + buf * 64 * SV) * 4;
#pragma unroll
        for (int j = 0; j < 4; j++) {
            const int c = tid + j * 256;
            const int row = c >> 4, c4 = (c & 15) * 4;
            cpa16(kb + (row * SQP + c4) * 4, ks + row * 64 + c4);
            cpa16(vb + (row * SV + c4) * 4, vs + row * 64 + c4);
        }
    };

    const int nkt = 2 * qt + 2;
    load_tile(0, 0); CP_COMMIT();

    const uint32_t* qsrc = Qg + ((size_t)bh * Tn + q0) * HDn;
    for (int i = tid; i < 128 * 16; i += 256) {
        const int row = i >> 4, c4 = (i & 15) * 4;
        *(uint4*)&Qs[row * SQP + c4] = *(const uint4*)(qsrc + row * 64 + c4);
    }
    __syncthreads();

    uint32_t aq[8][4];
#pragma unroll
    for (int k = 0; k < 8; k++) {
        aq[k][0] = Qs[(w0 + grp) * SQP + k * 8 + tig];
        aq[k][1] = Qs[(w0 + grp + 8) * SQP + k * 8 + tig];
        aq[k][2] = Qs[(w0 + grp) * SQP + k * 8 + tig + 4];
        aq[k][3] = Qs[(w0 + grp + 8) * SQP + k * 8 + tig + 4];
    }
    __syncthreads();

    float o[8][4];
#pragma unroll
    for (int n = 0; n < 8; n++)
#pragma unroll
        for (int v = 0; v < 4; v++) o[n][v] = 0.0f;
    float m0r = -1e30f, m1r = -1e30f, l0 = 0.0f, l1 = 0.0f;

    const int row0 = q0 + w0 + grp;
    const int row1 = row0 + 8;

    for (int kt = 0; kt < nkt; kt++) {
        __syncthreads();
        if (kt + 1 < nkt) load_tile(kt + 1, (kt + 1) & 1);
        CP_COMMIT();
        CP_WAIT1();
        __syncthreads();

        const uint32_t* Ks = sh + FL_K0 + (kt & 1) * 64 * SQP;
        const uint32_t* Vs = sh + FL_V0 + (kt & 1) * 64 * SV;

        const int kb = kt * 64;
        const bool active = (kb <= q0 + w0 + 15);
        if (active) {
            float s[8][4];
#pragma unroll
            for (int n = 0; n < 8; n++)
#pragma unroll
                for (int v = 0; v < 4; v++) s[n][v] = 0.0f;
#pragma unroll
            for (int k = 0; k < 8; k++) {
#pragma unroll
                for (int n = 0; n < 8; n++) {
                    const uint32_t* kp = &Ks[(n * 8 + grp) * SQP + k * 8 + tig];
                    mma_tf32(s[n], aq[k], kp[0], kp[4]);
                }
            }

            if (kb + 63 > row0) {
#pragma unroll
                for (int n = 0; n < 8; n++) {
                    const int col = kb + n * 8 + tig * 2;
                    if (col > row0)     s[n][0] = -1e30f;
                    if (col + 1 > row0) s[n][1] = -1e30f;
                    if (col > row1)     s[n][2] = -1e30f;
                    if (col + 1 > row1) s[n][3] = -1e30f;
                }
            }

            float tm0 = -1e30f, tm1 = -1e30f;
#pragma unroll
            for (int n = 0; n < 8; n++) {
                tm0 = fmaxf(tm0, fmaxf(s[n][0], s[n][1]));
                tm1 = fmaxf(tm1, fmaxf(s[n][2], s[n][3]));
            }
            tm0 = fmaxf(tm0, __shfl_xor_sync(0xffffffff, tm0, 1));
            tm0 = fmaxf(tm0, __shfl_xor_sync(0xffffffff, tm0, 2));
            tm1 = fmaxf(tm1, __shfl_xor_sync(0xffffffff, tm1, 1));
            tm1 = fmaxf(tm1, __shfl_xor_sync(0xffffffff, tm1, 2));

            const float nm0 = fmaxf(m0r, tm0);
            const float nm1 = fmaxf(m1r, tm1);
            const float c0 = __expf(m0r - nm0);
            const float c1 = __expf(m1r - nm1);
            m0r = nm0; m1r = nm1;

            float ps0 = 0.0f, ps1 = 0.0f;
            uint32_t* p0row = &Qs[(w0 + grp) * SQP];
            uint32_t* p1row = &Qs[(w0 + grp + 8) * SQP];
#pragma unroll
            for (int n = 0; n < 8; n++) {
                const float e0 = __expf(s[n][0] - nm0);
                const float e1 = __expf(s[n][1] - nm0);
                const float e2 = __expf(s[n][2] - nm1);
                const float e3 = __expf(s[n][3] - nm1);
                ps0 += e0 + e1;
                ps1 += e2 + e3;
                const int c = n * 8 + tig * 2;
                p0row[c]     = f2tf32(e0);
                p0row[c + 1] = f2tf32(e1);
                p1row[c]     = f2tf32(e2);
                p1row[c + 1] = f2tf32(e3);
            }
            ps0 += __shfl_xor_sync(0xffffffff, ps0, 1);
            ps0 += __shfl_xor_sync(0xffffffff, ps0, 2);
            ps1 += __shfl_xor_sync(0xffffffff, ps1, 1);
            ps1 += __shfl_xor_sync(0xffffffff, ps1, 2);
            l0 = l0 * c0 + ps0;
            l1 = l1 * c1 + ps1;

#pragma unroll
            for (int n = 0; n < 8; n++) {
                o[n][0] *= c0; o[n][1] *= c0;
                o[n][2] *= c1; o[n][3] *= c1;
            }
            __syncwarp();

#pragma unroll
            for (int k = 0; k < 8; k++) {
                uint32_t ap[4];
                ap[0] = Qs[(w0 + grp) * SQP + k * 8 + tig];
                ap[1] = Qs[(w0 + grp + 8) * SQP + k * 8 + tig];
                ap[2] = Qs[(w0 + grp) * SQP + k * 8 + tig + 4];
                ap[3] = Qs[(w0 + grp + 8) * SQP + k * 8 + tig + 4];
#pragma unroll
                for (int n = 0; n < 8; n++) {
                    const uint32_t b0 = Vs[(k * 8 + tig) * SV + n * 8 + grp];
                    const uint32_t b1 = Vs[(k * 8 + tig + 4) * SV + n * 8 + grp];
                    mma_tf32(o[n], ap, b0, b1);
                }
            }
            __syncwarp();
        }
    }

    // epilogue: write k-permuted 16-block layout (pos(c) = (c&3)*4 + (c>>2)&3)
    const float inv0 = 1.0f / l0;
    const float inv1 = 1.0f / l1;
    const int b = bh / Hn, h = bh % Hn;
    float* dst0 = Ob + ((size_t)(b * Tn) + row0) * Cn + h * HDn;
    float* dst1 = dst0 + (size_t)8 * Cn;
#pragma unroll
    for (int n = 0; n < 8; n++) {
        const int c = n * 8 + tig * 2;
        const int cp0 = (c & ~15) | ((c & 3) << 2) | ((c >> 2) & 3);
        const int c2 = c + 1;
        const int cp1 = (c2 & ~15) | ((c2 & 3) << 2) | ((c2 >> 2) & 3);
        dst0[cp0] = __uint_as_float(f2tf32(o[n][0] * inv0));
        dst0[cp1] = __uint_as_float(f2tf32(o[n][1] * inv0));
        dst1[cp0] = __uint_as_float(f2tf32(o[n][2] * inv1));
        dst1[cp1] = __uint_as_float(f2tf32(o[n][3] * inv1));
    }
}

// ---------------------------------------------------------------------------
extern "C" void kernel_launch(void* const* d_in, const int* in_sizes, int n_in,
                              void* d_out, int out_size)
{
    const float* x  = (const float*)d_in[0];
    const float* Wq = (const float*)d_in[1];
    const float* bq = (const float*)d_in[2];
    const float* Wk = (const float*)d_in[3];
    const float* bk = (const float*)d_in[4];
    const float* Wv = (const float*)d_in[5];
    const float* bv = (const float*)d_in[6];
    const float* Wp = (const float*)d_in[7];
    const float* bp = (const float*)d_in[8];
    float* out = (float*)d_out;

    float *pq, *pk, *pv, *pa;
    uint32_t *pxt, *pwq, *pwk, *pwv, *pwp;
    cudaGetSymbolAddress((void**)&pq, g_q);
    cudaGetSymbolAddress((void**)&pk, g_k);
    cudaGetSymbolAddress((void**)&pv, g_v);
    cudaGetSymbolAddress((void**)&pa, g_a);
    cudaGetSymbolAddress((void**)&pxt, g_xt);
    cudaGetSymbolAddress((void**)&pwq, g_wqt);
    cudaGetSymbolAddress((void**)&pwk, g_wkt);
    cudaGetSymbolAddress((void**)&pwv, g_wvt);
    cudaGetSymbolAddress((void**)&pwp, g_wpt);

    cudaFuncSetAttribute(tf32_gemm4<0>,
        cudaFuncAttributeMaxDynamicSharedMemorySize, GEMM_SMEM);
    cudaFuncSetAttribute(tf32_gemm4<1>,
        cudaFuncAttributeMaxDynamicSharedMemorySize, GEMM_SMEM);
    cudaFuncSetAttribute(flash_tc2,
        cudaFuncAttributeMaxDynamicSharedMemorySize, FLASH_SMEM);

    prep_cvt<<<2048, 256>>>(x, Wq, Wk, Wv, Wp,
                            pxt, pwq, pwk, pwv, pwp);

    // Fused QKV: gridDim.z selects the weight/bias/output triple
    dim3 gq(Cn / 128, Mrows / 128, 3);   // (8, 32, 3)
    tf32_gemm4<0><<<gq, 256, GEMM_SMEM>>>(pxt, pwq, pwk, pwv,
                                          bq, bk, bv, pq, pk, pv);

    dim3 fg(Tn / 128, Bn * Hn);          // (16, 32)
    flash_tc2<<<fg, 256, FLASH_SMEM>>>((const uint32_t*)pq, (const uint32_t*)pk,
                                       (const uint32_t*)pv, pa);

    dim3 gp(Cn / 128, Mrows / 128, 1);   // (8, 32, 1)
    tf32_gemm4<1><<<gp, 256, GEMM_SMEM>>>((const uint32_t*)pa, pwp, pwp, pwp,
                                          bp, bp, bp, out, out, out);
}

// round 7
// speedup vs baseline: 1.3098x; 1.0789x over previous
#include <cuda_runtime.h>
#include <stdint.h>

// Problem dims
#define Bn 2
#define Tn 2048
#define Cn 1024
#define Hn 16
#define HDn 64
#define Mrows (Bn * Tn)   // 4096

// Scratch (allocation-free: __device__ globals)
__device__ float g_q[Bn * Hn * Tn * HDn];   // tf32-rounded, pre-scaled by 1/8
__device__ float g_k[Bn * Hn * Tn * HDn];   // tf32-rounded
__device__ float g_v[Bn * Hn * Tn * HDn];   // tf32-rounded
__device__ float g_a[Bn * Tn * Cn];         // flash out, tf32, k-permuted blocks
__device__ uint32_t g_xt[Mrows * Cn];       // x  tf32, k-permuted 16-blocks
__device__ uint32_t g_wqt[Cn * Cn];         // weights tf32, k-permuted
__device__ uint32_t g_wkt[Cn * Cn];
__device__ uint32_t g_wvt[Cn * Cn];
__device__ uint32_t g_wpt[Cn * Cn];

__device__ __forceinline__ uint32_t f2tf32(float x) {
    uint32_t y;
    asm("cvt.rna.tf32.f32 %0, %1;" : "=r"(y) : "f"(x));
    return y;
}

__device__ __forceinline__ void mma_tf32(float* c, const uint32_t* a,
                                         uint32_t b0, uint32_t b1) {
    asm volatile(
        "mma.sync.aligned.m16n8k8.row.col.f32.tf32.tf32.f32 "
        "{%0,%1,%2,%3}, {%4,%5,%6,%7}, {%8,%9}, {%0,%1,%2,%3};"
        : "+f"(c[0]), "+f"(c[1]), "+f"(c[2]), "+f"(c[3])
        : "r"(a[0]), "r"(a[1]), "r"(a[2]), "r"(a[3]), "r"(b0), "r"(b1));
}

__device__ __forceinline__ void cpa16(uint32_t dst, const void* src) {
    asm volatile("cp.async.ca.shared.global [%0], [%1], 16;" :: "r"(dst), "l"(src));
}
#define CP_COMMIT() asm volatile("cp.async.commit_group;")
#define CP_WAIT1()  asm volatile("cp.async.wait_group 1;")

// ---------------------------------------------------------------------------
// prep: tf32-round AND k-permute each 16-float block (4x4 transpose within
// block) so a fragment thread's k-set {tig, tig+4, tig+8, tig+12} is
// contiguous. One thread per 16-float block.
// ---------------------------------------------------------------------------
__global__ __launch_bounds__(256)
void prep_cvt(const float* __restrict__ x,
              const float* __restrict__ wq, const float* __restrict__ wk,
              const float* __restrict__ wv, const float* __restrict__ wp,
              uint32_t* __restrict__ xt,
              uint32_t* __restrict__ wqt, uint32_t* __restrict__ wkt,
              uint32_t* __restrict__ wvt, uint32_t* __restrict__ wpt)
{
    const int i = blockIdx.x * 256 + threadIdx.x;   // 0 .. 2^19-1
    const float* src; uint32_t* dst; int off;
    if (i < (1 << 18)) { src = x; dst = xt; off = i; }
    else {
        const int j = i - (1 << 18);
        const int w = j >> 16;
        off = j & 65535;
        src = (w == 0) ? wq : (w == 1) ? wk : (w == 2) ? wv : wp;
        dst = (w == 0) ? wqt : (w == 1) ? wkt : (w == 2) ? wvt : wpt;
    }
    const float4* s = (const float4*)src + (size_t)off * 4;
    float4 v0 = s[0], v1 = s[1], v2 = s[2], v3 = s[3];
    uint4* d = (uint4*)dst + (size_t)off * 4;
    uint4 u0 = {f2tf32(v0.x), f2tf32(v1.x), f2tf32(v2.x), f2tf32(v3.x)};
    uint4 u1 = {f2tf32(v0.y), f2tf32(v1.y), f2tf32(v2.y), f2tf32(v3.y)};
    uint4 u2 = {f2tf32(v0.z), f2tf32(v1.z), f2tf32(v2.z), f2tf32(v3.z)};
    uint4 u3 = {f2tf32(v0.w), f2tf32(v1.w), f2tf32(v2.w), f2tf32(v3.w)};
    d[0] = u0; d[1] = u1; d[2] = u2; d[3] = u3;
}

// ---------------------------------------------------------------------------
// tf32 GEMM v5: D = (A @ W^T + bias) * scale ; inputs tf32 + k-permuted.
//   256 thr (8 warps), block 128x128, warp tile 64x32.
//   BK=32 (two 16-k sub-tiles, each R6's proven swizzled layout),
//   3-stage cp.async (32KB/stage), wait_group 1 => ~2-iteration lead.
// ---------------------------------------------------------------------------
#define SUBW 2048                        // words per 16-k sub-tile (128*16)
#define STGW (4 * SUBW)                  // words per stage (A sub0/1, W sub0/1)
#define GEMM_SMEM (3 * STGW * 4)         // 98304 bytes

template <int MODE>
__global__ __launch_bounds__(256, 2)
void tf32_gemm5(const uint32_t* __restrict__ A,
                const uint32_t* __restrict__ W0, const uint32_t* __restrict__ W1,
                const uint32_t* __restrict__ W2,
                const float* __restrict__ b0p, const float* __restrict__ b1p,
                const float* __restrict__ b2p,
                float* __restrict__ D0, float* __restrict__ D1,
                float* __restrict__ D2)
{
    extern __shared__ uint32_t smem[];
    const int z = blockIdx.z;
    const uint32_t* W = (z == 0) ? W0 : ((z == 1) ? W1 : W2);
    const float* bias = (z == 0) ? b0p : ((z == 1) ? b1p : b2p);
    float* D = (z == 0) ? D0 : ((z == 1) ? D1 : D2);
    const float scale = (MODE == 0 && z == 0) ? 0.125f : 1.0f;

    const int tid  = threadIdx.x;
    const int lane = tid & 31;
    const int wid  = tid >> 5;
    const int m0   = blockIdx.y * 128;
    const int n0   = blockIdx.x * 128;
    const int wm   = (wid & 1) * 64;
    const int wn   = (wid >> 1) * 32;
    const int grp  = lane >> 2;
    const int tig  = lane & 3;

    // global->smem: thread writes 2 chunks per sub-tile per tensor (8 cpa16)
    const int lr = tid >> 1;               // 0..127
    const int c0 = (tid & 1) * 2;          // chunks c0, c0+1
    const uint32_t* Ag = A + (size_t)(m0 + lr) * Cn;
    const uint32_t* Wg = W + (size_t)(n0 + lr) * Cn;
    const uint32_t shb = (uint32_t)__cvta_generic_to_shared(smem);
    const uint32_t sw  = lr & 3;
    const uint32_t d0 = (lr * 16 + ((c0 + 0) ^ sw) * 4) * 4;  // byte offsets
    const uint32_t d1 = (lr * 16 + ((c0 + 1) ^ sw) * 4) * 4;

    auto loadstage = [&](int it, int slot) {
        const uint32_t s0 = shb + slot * (STGW * 4);
        const uint32_t* as = Ag + it * 32 + c0 * 4;
        const uint32_t* ws = Wg + it * 32 + c0 * 4;
        // A sub0 / sub1
        cpa16(s0 + d0, as);
        cpa16(s0 + d1, as + 4);
        cpa16(s0 + SUBW * 4 + d0, as + 16);
        cpa16(s0 + SUBW * 4 + d1, as + 20);
        // W sub0 / sub1
        cpa16(s0 + 2 * SUBW * 4 + d0, ws);
        cpa16(s0 + 2 * SUBW * 4 + d1, ws + 4);
        cpa16(s0 + 3 * SUBW * 4 + d0, ws + 16);
        cpa16(s0 + 3 * SUBW * 4 + d1, ws + 20);
    };

    float acc[4][4][4];
#pragma unroll
    for (int i = 0; i < 4; i++)
#pragma unroll
        for (int j = 0; j < 4; j++)
#pragma unroll
            for (int v = 0; v < 4; v++) acc[i][j][v] = 0.0f;

    loadstage(0, 0); CP_COMMIT();
    loadstage(1, 1); CP_COMMIT();

    const int csel = (tig ^ (grp & 3)) * 4;   // swizzled chunk offset (words)

    for (int it = 0; it < 32; it++) {
        CP_WAIT1();
        __syncthreads();
        if (it + 2 < 32) loadstage(it + 2, (it + 2) % 3);
        CP_COMMIT();

        const uint32_t* St = smem + (it % 3) * STGW;
#pragma unroll
        for (int half = 0; half < 2; half++) {
            const uint32_t* As_ = St + half * SUBW;
            const uint32_t* Bs_ = St + 2 * SUBW + half * SUBW;

            uint4 aA[4][2];
            uint4 bB[4];
#pragma unroll
            for (int mt = 0; mt < 4; mt++) {
                const int r = wm + mt * 16 + grp;
                aA[mt][0] = *(const uint4*)&As_[r * 16 + csel];
                aA[mt][1] = *(const uint4*)&As_[(r + 8) * 16 + csel];
            }
#pragma unroll
            for (int nt = 0; nt < 4; nt++) {
                const int r = wn + nt * 8 + grp;
                bB[nt] = *(const uint4*)&Bs_[r * 16 + csel];
            }

#pragma unroll
            for (int ks = 0; ks < 2; ks++) {
#pragma unroll
                for (int mt = 0; mt < 4; mt++) {
                    uint32_t af[4];
                    if (ks == 0) {
                        af[0] = aA[mt][0].x; af[1] = aA[mt][1].x;
                        af[2] = aA[mt][0].y; af[3] = aA[mt][1].y;
                    } else {
                        af[0] = aA[mt][0].z; af[1] = aA[mt][1].z;
                        af[2] = aA[mt][0].w; af[3] = aA[mt][1].w;
                    }
#pragma unroll
                    for (int nt = 0; nt < 4; nt++) {
                        const uint32_t b0 = (ks == 0) ? bB[nt].x : bB[nt].z;
                        const uint32_t b1 = (ks == 0) ? bB[nt].y : bB[nt].w;
                        mma_tf32(acc[mt][nt], af, b0, b1);
                    }
                }
            }
        }
    }

#pragma unroll
    for (int mt = 0; mt < 4; mt++) {
        const int r0 = m0 + wm + mt * 16 + grp;
#pragma unroll
        for (int nt = 0; nt < 4; nt++) {
            const int gc = n0 + wn + nt * 8 + tig * 2;
#pragma unroll
            for (int vp = 0; vp < 2; vp++) {          // v pair {0,1} / {2,3}
                const int gr = r0 + vp * 8;
                float v0 = (acc[mt][nt][vp * 2 + 0] + bias[gc]) * scale;
                float v1 = (acc[mt][nt][vp * 2 + 1] + bias[gc + 1]) * scale;
                if (MODE == 0) {
                    const int b = gr / Tn, t = gr % Tn;
                    const int h = gc >> 6, d = gc & 63;
                    float2 p = {__uint_as_float(f2tf32(v0)),
                                __uint_as_float(f2tf32(v1))};
                    *(float2*)&D[(((size_t)(b * Hn + h)) * Tn + t) * HDn + d] = p;
                } else {
                    float2 p = {v0, v1};
                    *(float2*)&D[(size_t)gr * Cn + gc] = p;
                }
            }
        }
    }
}

// ---------------------------------------------------------------------------
// Tensor-core flash attention v2 (causal) — unchanged (validated).
// Epilogue writes g_a with the k-permuted 16-block layout for the proj GEMM.
// ---------------------------------------------------------------------------
#define SQP 68
#define SV  72
#define FL_K0 (128 * SQP)
#define FL_V0 (FL_K0 + 2 * 64 * SQP)
#define FLASH_SMEM ((FL_V0 + 2 * 64 * SV) * 4)  // 106496 bytes

__global__ __launch_bounds__(256)
void flash_tc2(const uint32_t* __restrict__ Qg, const uint32_t* __restrict__ Kg,
               const uint32_t* __restrict__ Vg, float* __restrict__ Ob)
{
    extern __shared__ uint32_t sh[];
    uint32_t* Qs = sh;

    const int bh  = blockIdx.y;
    const int qt  = (gridDim.x - 1) - blockIdx.x;   // heavy tiles first
    const int tid = threadIdx.x;
    const int lane = tid & 31;
    const int wid  = tid >> 5;
    const int grp  = lane >> 2;
    const int tig  = lane & 3;
    const int q0   = qt * 128;
    const int w0   = wid * 16;

    const uint32_t shb = (uint32_t)__cvta_generic_to_shared(sh);
    const uint32_t* Kbh = Kg + (size_t)bh * Tn * HDn;
    const uint32_t* Vbh = Vg + (size_t)bh * Tn * HDn;

    auto load_tile = [&](int kt, int buf) {
        const uint32_t* ks = Kbh + (size_t)kt * 64 * HDn;
        const uint32_t* vs = Vbh + (size_t)kt * 64 * HDn;
        const uint32_t kb = shb + (FL_K0 + buf * 64 * SQP) * 4;
        const uint32_t vb = shb + (FL_V0 + buf * 64 * SV) * 4;
#pragma unroll
        for (int j = 0; j < 4; j++) {
            const int c = tid + j * 256;
            const int row = c >> 4, c4 = (c & 15) * 4;
            cpa16(kb + (row * SQP + c4) * 4, ks + row * 64 + c4);
            cpa16(vb + (row * SV + c4) * 4, vs + row * 64 + c4);
        }
    };

    const int nkt = 2 * qt + 2;
    load_tile(0, 0); CP_COMMIT();

    const uint32_t* qsrc = Qg + ((size_t)bh * Tn + q0) * HDn;
    for (int i = tid; i < 128 * 16; i += 256) {
        const int row = i >> 4, c4 = (i & 15) * 4;
        *(uint4*)&Qs[row * SQP + c4] = *(const uint4*)(qsrc + row * 64 + c4);
    }
    __syncthreads();

    uint32_t aq[8][4];
#pragma unroll
    for (int k = 0; k < 8; k++) {
        aq[k][0] = Qs[(w0 + grp) * SQP + k * 8 + tig];
        aq[k][1] = Qs[(w0 + grp + 8) * SQP + k * 8 + tig];
        aq[k][2] = Qs[(w0 + grp) * SQP + k * 8 + tig + 4];
        aq[k][3] = Qs[(w0 + grp + 8) * SQP + k * 8 + tig + 4];
    }
    __syncthreads();

    float o[8][4];
#pragma unroll
    for (int n = 0; n < 8; n++)
#pragma unroll
        for (int v = 0; v < 4; v++) o[n][v] = 0.0f;
    float m0r = -1e30f, m1r = -1e30f, l0 = 0.0f, l1 = 0.0f;

    const int row0 = q0 + w0 + grp;
    const int row1 = row0 + 8;

    for (int kt = 0; kt < nkt; kt++) {
        __syncthreads();
        if (kt + 1 < nkt) load_tile(kt + 1, (kt + 1) & 1);
        CP_COMMIT();
        CP_WAIT1();
        __syncthreads();

        const uint32_t* Ks = sh + FL_K0 + (kt & 1) * 64 * SQP;
        const uint32_t* Vs = sh + FL_V0 + (kt & 1) * 64 * SV;

        const int kb = kt * 64;
        const bool active = (kb <= q0 + w0 + 15);
        if (active) {
            float s[8][4];
#pragma unroll
            for (int n = 0; n < 8; n++)
#pragma unroll
                for (int v = 0; v < 4; v++) s[n][v] = 0.0f;
#pragma unroll
            for (int k = 0; k < 8; k++) {
#pragma unroll
                for (int n = 0; n < 8; n++) {
                    const uint32_t* kp = &Ks[(n * 8 + grp) * SQP + k * 8 + tig];
                    mma_tf32(s[n], aq[k], kp[0], kp[4]);
                }
            }

            if (kb + 63 > row0) {
#pragma unroll
                for (int n = 0; n < 8; n++) {
                    const int col = kb + n * 8 + tig * 2;
                    if (col > row0)     s[n][0] = -1e30f;
                    if (col + 1 > row0) s[n][1] = -1e30f;
                    if (col > row1)     s[n][2] = -1e30f;
                    if (col + 1 > row1) s[n][3] = -1e30f;
                }
            }

            float tm0 = -1e30f, tm1 = -1e30f;
#pragma unroll
            for (int n = 0; n < 8; n++) {
                tm0 = fmaxf(tm0, fmaxf(s[n][0], s[n][1]));
                tm1 = fmaxf(tm1, fmaxf(s[n][2], s[n][3]));
            }
            tm0 = fmaxf(tm0, __shfl_xor_sync(0xffffffff, tm0, 1));
            tm0 = fmaxf(tm0, __shfl_xor_sync(0xffffffff, tm0, 2));
            tm1 = fmaxf(tm1, __shfl_xor_sync(0xffffffff, tm1, 1));
            tm1 = fmaxf(tm1, __shfl_xor_sync(0xffffffff, tm1, 2));

            const float nm0 = fmaxf(m0r, tm0);
            const float nm1 = fmaxf(m1r, tm1);
            const float c0 = __expf(m0r - nm0);
            const float c1 = __expf(m1r - nm1);
            m0r = nm0; m1r = nm1;

            float ps0 = 0.0f, ps1 = 0.0f;
            uint32_t* p0row = &Qs[(w0 + grp) * SQP];
            uint32_t* p1row = &Qs[(w0 + grp + 8) * SQP];
#pragma unroll
            for (int n = 0; n < 8; n++) {
                const float e0 = __expf(s[n][0] - nm0);
                const float e1 = __expf(s[n][1] - nm0);
                const float e2 = __expf(s[n][2] - nm1);
                const float e3 = __expf(s[n][3] - nm1);
                ps0 += e0 + e1;
                ps1 += e2 + e3;
                const int c = n * 8 + tig * 2;
                p0row[c]     = f2tf32(e0);
                p0row[c + 1] = f2tf32(e1);
                p1row[c]     = f2tf32(e2);
                p1row[c + 1] = f2tf32(e3);
            }
            ps0 += __shfl_xor_sync(0xffffffff, ps0, 1);
            ps0 += __shfl_xor_sync(0xffffffff, ps0, 2);
            ps1 += __shfl_xor_sync(0xffffffff, ps1, 1);
            ps1 += __shfl_xor_sync(0xffffffff, ps1, 2);
            l0 = l0 * c0 + ps0;
            l1 = l1 * c1 + ps1;

#pragma unroll
            for (int n = 0; n < 8; n++) {
                o[n][0] *= c0; o[n][1] *= c0;
                o[n][2] *= c1; o[n][3] *= c1;
            }
            __syncwarp();

#pragma unroll
            for (int k = 0; k < 8; k++) {
                uint32_t ap[4];
                ap[0] = Qs[(w0 + grp) * SQP + k * 8 + tig];
                ap[1] = Qs[(w0 + grp + 8) * SQP + k * 8 + tig];
                ap[2] = Qs[(w0 + grp) * SQP + k * 8 + tig + 4];
                ap[3] = Qs[(w0 + grp + 8) * SQP + k * 8 + tig + 4];
#pragma unroll
                for (int n = 0; n < 8; n++) {
                    const uint32_t b0 = Vs[(k * 8 + tig) * SV + n * 8 + grp];
                    const uint32_t b1 = Vs[(k * 8 + tig + 4) * SV + n * 8 + grp];
                    mma_tf32(o[n], ap, b0, b1);
                }
            }
            __syncwarp();
        }
    }

    // epilogue: write k-permuted 16-block layout (pos(c) = (c&3)*4 + (c>>2)&3)
    const float inv0 = 1.0f / l0;
    const float inv1 = 1.0f / l1;
    const int b = bh / Hn, h = bh % Hn;
    float* dst0 = Ob + ((size_t)(b * Tn) + row0) * Cn + h * HDn;
    float* dst1 = dst0 + (size_t)8 * Cn;
#pragma unroll
    for (int n = 0; n < 8; n++) {
        const int c = n * 8 + tig * 2;
        const int cp0 = (c & ~15) | ((c & 3) << 2) | ((c >> 2) & 3);
        const int c2 = c + 1;
        const int cp1 = (c2 & ~15) | ((c2 & 3) << 2) | ((c2 >> 2) & 3);
        dst0[cp0] = __uint_as_float(f2tf32(o[n][0] * inv0));
        dst0[cp1] = __uint_as_float(f2tf32(o[n][1] * inv0));
        dst1[cp0] = __uint_as_float(f2tf32(o[n][2] * inv1));
        dst1[cp1] = __uint_as_float(f2tf32(o[n][3] * inv1));
    }
}

// ---------------------------------------------------------------------------
extern "C" void kernel_launch(void* const* d_in, const int* in_sizes, int n_in,
                              void* d_out, int out_size)
{
    const float* x  = (const float*)d_in[0];
    const float* Wq = (const float*)d_in[1];
    const float* bq = (const float*)d_in[2];
    const float* Wk = (const float*)d_in[3];
    const float* bk = (const float*)d_in[4];
    const float* Wv = (const float*)d_in[5];
    const float* bv = (const float*)d_in[6];
    const float* Wp = (const float*)d_in[7];
    const float* bp = (const float*)d_in[8];
    float* out = (float*)d_out;

    float *pq, *pk, *pv, *pa;
    uint32_t *pxt, *pwq, *pwk, *pwv, *pwp;
    cudaGetSymbolAddress((void**)&pq, g_q);
    cudaGetSymbolAddress((void**)&pk, g_k);
    cudaGetSymbolAddress((void**)&pv, g_v);
    cudaGetSymbolAddress((void**)&pa, g_a);
    cudaGetSymbolAddress((void**)&pxt, g_xt);
    cudaGetSymbolAddress((void**)&pwq, g_wqt);
    cudaGetSymbolAddress((void**)&pwk, g_wkt);
    cudaGetSymbolAddress((void**)&pwv, g_wvt);
    cudaGetSymbolAddress((void**)&pwp, g_wpt);

    cudaFuncSetAttribute(tf32_gemm5<0>,
        cudaFuncAttributeMaxDynamicSharedMemorySize, GEMM_SMEM);
    cudaFuncSetAttribute(tf32_gemm5<1>,
        cudaFuncAttributeMaxDynamicSharedMemorySize, GEMM_SMEM);
    cudaFuncSetAttribute(flash_tc2,
        cudaFuncAttributeMaxDynamicSharedMemorySize, FLASH_SMEM);

    prep_cvt<<<2048, 256>>>(x, Wq, Wk, Wv, Wp,
                            pxt, pwq, pwk, pwv, pwp);

    // Fused QKV: gridDim.z selects the weight/bias/output triple
    dim3 gq(Cn / 128, Mrows / 128, 3);   // (8, 32, 3)
    tf32_gemm5<0><<<gq, 256, GEMM_SMEM>>>(pxt, pwq, pwk, pwv,
                                          bq, bk, bv, pq, pk, pv);

    dim3 fg(Tn / 128, Bn * Hn);          // (16, 32)
    flash_tc2<<<fg, 256, FLASH_SMEM>>>((const uint32_t*)pq, (const uint32_t*)pk,
                                       (const uint32_t*)pv, pa);

    dim3 gp(Cn / 128, Mrows / 128, 1);   // (8, 32, 1)
    tf32_gemm5<1><<<gp, 256, GEMM_SMEM>>>((const uint32_t*)pa, pwp, pwp, pwp,
                                          bp, bp, bp, out, out, out);
}

// round 9
// speedup vs baseline: 1.8150x; 1.3857x over previous
#include <cuda_runtime.h>
#include <cuda_fp16.h>
#include <stdint.h>

// Problem dims
#define Bn 2
#define Tn 2048
#define Cn 1024
#define Hn 16
#define HDn 64
#define Mrows (Bn * Tn)   // 4096
#define RW 512            // words per row (1024 halfs)

// Scratch (allocation-free: __device__ globals)
__device__ float g_q[Bn * Hn * Tn * HDn];   // tf32-rounded fp32 (flash input)
__device__ float g_k[Bn * Hn * Tn * HDn];
__device__ float g_v[Bn * Hn * Tn * HDn];
__device__ uint32_t g_a[Mrows * RW];        // flash out: fp16, permuted blocks
__device__ uint32_t g_xt[Mrows * RW];       // x  fp16, permuted 32-half blocks
__device__ uint32_t g_wqt[Cn * RW];         // weights fp16, permuted
__device__ uint32_t g_wkt[Cn * RW];
__device__ uint32_t g_wvt[Cn * RW];
__device__ uint32_t g_wpt[Cn * RW];

__device__ __forceinline__ uint32_t f2tf32(float x) {
    uint32_t y;
    asm("cvt.rna.tf32.f32 %0, %1;" : "=r"(y) : "f"(x));
    return y;
}
__device__ __forceinline__ uint32_t packh2(float a, float b) {
    __half2 h = __float22half2_rn(make_float2(a, b));
    return *(uint32_t*)&h;
}

// fp16 tensor mma: D(16x8 f32) += A(16x16 f16) B(16x8 f16)
__device__ __forceinline__ void mma_f16(float* c, uint32_t a0, uint32_t a1,
                                        uint32_t a2, uint32_t a3,
                                        uint32_t b0, uint32_t b1) {
    asm volatile(
        "mma.sync.aligned.m16n8k16.row.col.f32.f16.f16.f32 "
        "{%0,%1,%2,%3}, {%4,%5,%6,%7}, {%8,%9}, {%0,%1,%2,%3};"
        : "+f"(c[0]), "+f"(c[1]), "+f"(c[2]), "+f"(c[3])
        : "r"(a0), "r"(a1), "r"(a2), "r"(a3), "r"(b0), "r"(b1));
}

// flash-side tf32 mma (unchanged, validated)
__device__ __forceinline__ void mma_tf32(float* c, const uint32_t* a,
                                         uint32_t b0, uint32_t b1) {
    asm volatile(
        "mma.sync.aligned.m16n8k8.row.col.f32.tf32.tf32.f32 "
        "{%0,%1,%2,%3}, {%4,%5,%6,%7}, {%8,%9}, {%0,%1,%2,%3};"
        : "+f"(c[0]), "+f"(c[1]), "+f"(c[2]), "+f"(c[3])
        : "r"(a[0]), "r"(a[1]), "r"(a[2]), "r"(a[3]), "r"(b0), "r"(b1));
}

__device__ __forceinline__ void cpa16(uint32_t dst, const void* src) {
    asm volatile("cp.async.ca.shared.global [%0], [%1], 16;" :: "r"(dst), "l"(src));
}
#define CP_COMMIT() asm volatile("cp.async.commit_group;")
#define CP_WAIT1()  asm volatile("cp.async.wait_group 1;")

// ---------------------------------------------------------------------------
// prep: fp32 -> fp16 with per-32-half-block word permutation:
//   natural word j (halfs 2j,2j+1) of a 16-word block is stored at
//   slot(j) = (j&3)*4 + ((j>>3)&1)*2 + ((j>>2)&1)
// so an LDS.128 at word 4*tig yields {g0:w_tig, g0:w_tig+4, g1:w_tig,
// g1:w_tig+4} = the m16n8k16 fragment words for both k-phases.
// One thread per block (32 floats in, 16 words out).
// ---------------------------------------------------------------------------
__global__ __launch_bounds__(256)
void prep_cvt(const float* __restrict__ x,
              const float* __restrict__ wq, const float* __restrict__ wk,
              const float* __restrict__ wv, const float* __restrict__ wp,
              uint32_t* __restrict__ xt,
              uint32_t* __restrict__ wqt, uint32_t* __restrict__ wkt,
              uint32_t* __restrict__ wvt, uint32_t* __restrict__ wpt)
{
    const int i = blockIdx.x * 256 + threadIdx.x;   // 0 .. 2^18-1
    const float* src; uint32_t* dst; int off;
    if (i < (1 << 17)) { src = x; dst = xt; off = i; }
    else {
        const int j = i - (1 << 17);
        const int w = j >> 15;
        off = j & 32767;
        src = (w == 0) ? wq : (w == 1) ? wk : (w == 2) ? wv : wp;
        dst = (w == 0) ? wqt : (w == 1) ? wkt : (w == 2) ? wvt : wpt;
    }
    const float* s = src + (size_t)off * 32;
    float v[32];
#pragma unroll
    for (int q = 0; q < 8; q++) {
        float4 t = *(const float4*)(s + q * 4);
        v[q * 4 + 0] = t.x; v[q * 4 + 1] = t.y;
        v[q * 4 + 2] = t.z; v[q * 4 + 3] = t.w;
    }
    uint32_t w16[16];
#pragma unroll
    for (int j = 0; j < 16; j++) {
        const int slot = (j & 3) * 4 + (((j >> 3) & 1) << 1) + ((j >> 2) & 1);
        w16[slot] = packh2(v[2 * j], v[2 * j + 1]);
    }
    uint4* d = (uint4*)(dst + (size_t)off * 16);
#pragma unroll
    for (int q = 0; q < 4; q++)
        d[q] = make_uint4(w16[q * 4], w16[q * 4 + 1], w16[q * 4 + 2], w16[q * 4 + 3]);
}

// ---------------------------------------------------------------------------
// fp16 GEMM: D = (A @ W^T + bias) * scale ; inputs fp16, permuted blocks.
//   256 thr (8 warps), block 128x128, warp tile 64x32, m16n8k16.
//   BK=64 halfs = 2 sub-tiles of 32 halfs (16 words, XOR-swizzled chunks),
//   3-stage cp.async (32KB/stage), wait_group 1, 16 outer iterations.
// ---------------------------------------------------------------------------
#define SUBW 2048                        // words per sub-tile (128 rows * 16)
#define STGW (4 * SUBW)                  // stage: A sub0/1, W sub0/1
#define GEMM_SMEM (3 * STGW * 4)         // 98304 bytes

template <int MODE>
__global__ __launch_bounds__(256, 2)
void h16_gemm(const uint32_t* __restrict__ A,
              const uint32_t* __restrict__ W0, const uint32_t* __restrict__ W1,
              const uint32_t* __restrict__ W2,
              const float* __restrict__ b0p, const float* __restrict__ b1p,
              const float* __restrict__ b2p,
              float* __restrict__ D0, float* __restrict__ D1,
              float* __restrict__ D2)
{
    extern __shared__ uint32_t smem[];
    const int z = blockIdx.z;
    const uint32_t* W = (z == 0) ? W0 : ((z == 1) ? W1 : W2);
    const float* bias = (z == 0) ? b0p : ((z == 1) ? b1p : b2p);
    float* D = (z == 0) ? D0 : ((z == 1) ? D1 : D2);
    const float scale = (MODE == 0 && z == 0) ? 0.125f : 1.0f;

    const int tid  = threadIdx.x;
    const int lane = tid & 31;
    const int wid  = tid >> 5;
    const int m0   = blockIdx.y * 128;
    const int n0   = blockIdx.x * 128;
    const int wm   = (wid & 1) * 64;
    const int wn   = (wid >> 1) * 32;
    const int grp  = lane >> 2;
    const int tig  = lane & 3;

    const int lr = tid >> 1;               // 0..127
    const int c0 = (tid & 1) * 2;          // chunks c0, c0+1
    const uint32_t* Ag = A + (size_t)(m0 + lr) * RW;
    const uint32_t* Wg = W + (size_t)(n0 + lr) * RW;
    const uint32_t shb = (uint32_t)__cvta_generic_to_shared(smem);
    const uint32_t sw  = lr & 3;
    const uint32_t d0 = (lr * 16 + ((c0 + 0) ^ sw) * 4) * 4;  // byte offsets
    const uint32_t d1 = (lr * 16 + ((c0 + 1) ^ sw) * 4) * 4;

    auto loadstage = [&](int it, int slot) {
        const uint32_t s0 = shb + slot * (STGW * 4);
        const uint32_t* as = Ag + it * 32 + c0 * 4;   // 32 words per BK
        const uint32_t* ws = Wg + it * 32 + c0 * 4;
        cpa16(s0 + d0, as);
        cpa16(s0 + d1, as + 4);
        cpa16(s0 + SUBW * 4 + d0, as + 16);
        cpa16(s0 + SUBW * 4 + d1, as + 20);
        cpa16(s0 + 2 * SUBW * 4 + d0, ws);
        cpa16(s0 + 2 * SUBW * 4 + d1, ws + 4);
        cpa16(s0 + 3 * SUBW * 4 + d0, ws + 16);
        cpa16(s0 + 3 * SUBW * 4 + d1, ws + 20);
    };

    float acc[4][4][4];
#pragma unroll
    for (int i = 0; i < 4; i++)
#pragma unroll
        for (int j = 0; j < 4; j++)
#pragma unroll
            for (int v = 0; v < 4; v++) acc[i][j][v] = 0.0f;

    loadstage(0, 0); CP_COMMIT();
    loadstage(1, 1); CP_COMMIT();

    const int csel = (tig ^ (grp & 3)) * 4;

    for (int it = 0; it < 16; it++) {
        CP_WAIT1();
        __syncthreads();
        if (it + 2 < 16) loadstage(it + 2, (it + 2) % 3);
        CP_COMMIT();

        const uint32_t* St = smem + (it % 3) * STGW;
#pragma unroll
        for (int sub = 0; sub < 2; sub++) {
            const uint32_t* As_ = St + sub * SUBW;
            const uint32_t* Bs_ = St + 2 * SUBW + sub * SUBW;

            uint4 aA[4][2];
            uint4 bB[4];
#pragma unroll
            for (int mt = 0; mt < 4; mt++) {
                const int r = wm + mt * 16 + grp;
                aA[mt][0] = *(const uint4*)&As_[r * 16 + csel];
                aA[mt][1] = *(const uint4*)&As_[(r + 8) * 16 + csel];
            }
#pragma unroll
            for (int nt = 0; nt < 4; nt++) {
                const int r = wn + nt * 8 + grp;
                bB[nt] = *(const uint4*)&Bs_[r * 16 + csel];
            }

            // k-phase 0: .x/.y ; k-phase 1: .z/.w
#pragma unroll
            for (int mt = 0; mt < 4; mt++)
#pragma unroll
                for (int nt = 0; nt < 4; nt++)
                    mma_f16(acc[mt][nt],
                            aA[mt][0].x, aA[mt][1].x, aA[mt][0].y, aA[mt][1].y,
                            bB[nt].x, bB[nt].y);
#pragma unroll
            for (int mt = 0; mt < 4; mt++)
#pragma unroll
                for (int nt = 0; nt < 4; nt++)
                    mma_f16(acc[mt][nt],
                            aA[mt][0].z, aA[mt][1].z, aA[mt][0].w, aA[mt][1].w,
                            bB[nt].z, bB[nt].w);
        }
    }

#pragma unroll
    for (int mt = 0; mt < 4; mt++) {
        const int r0 = m0 + wm + mt * 16 + grp;
#pragma unroll
        for (int nt = 0; nt < 4; nt++) {
            const int gc = n0 + wn + nt * 8 + tig * 2;
#pragma unroll
            for (int vp = 0; vp < 2; vp++) {
                const int gr = r0 + vp * 8;
                float v0 = (acc[mt][nt][vp * 2 + 0] + bias[gc]) * scale;
                float v1 = (acc[mt][nt][vp * 2 + 1] + bias[gc + 1]) * scale;
                if (MODE == 0) {
                    const int b = gr / Tn, t = gr % Tn;
                    const int h = gc >> 6, d = gc & 63;
                    float2 p = {__uint_as_float(f2tf32(v0)),
                                __uint_as_float(f2tf32(v1))};
                    *(float2*)&D[(((size_t)(b * Hn + h)) * Tn + t) * HDn + d] = p;
                } else {
                    float2 p = {v0, v1};
                    *(float2*)&D[(size_t)gr * Cn + gc] = p;
                }
            }
        }
    }
}

// ---------------------------------------------------------------------------
// Tensor-core flash attention (causal), tf32 — internals unchanged
// (validated). Epilogue writes g_a as fp16 in the permuted-block layout.
// ---------------------------------------------------------------------------
#define SQP 68
#define SV  72
#define FL_K0 (128 * SQP)
#define FL_V0 (FL_K0 + 2 * 64 * SQP)
#define FLASH_SMEM ((FL_V0 + 2 * 64 * SV) * 4)  // 106496 bytes

__global__ __launch_bounds__(256)
void flash_tc2(const uint32_t* __restrict__ Qg, const uint32_t* __restrict__ Kg,
               const uint32_t* __restrict__ Vg, uint32_t* __restrict__ Ob)
{
    extern __shared__ uint32_t sh[];
    uint32_t* Qs = sh;

    const int bh  = blockIdx.y;
    const int qt  = (gridDim.x - 1) - blockIdx.x;   // heavy tiles first
    const int tid = threadIdx.x;
    const int lane = tid & 31;
    const int wid  = tid >> 5;
    const int grp  = lane >> 2;
    const int tig  = lane & 3;
    const int q0   = qt * 128;
    const int w0   = wid * 16;

    const uint32_t shb = (uint32_t)__cvta_generic_to_shared(sh);
    const uint32_t* Kbh = Kg + (size_t)bh * Tn * HDn;
    const uint32_t* Vbh = Vg + (size_t)bh * Tn * HDn;

    auto load_tile = [&](int kt, int buf) {
        const uint32_t* ks = Kbh + (size_t)kt * 64 * HDn;
        const uint32_t* vs = Vbh + (size_t)kt * 64 * HDn;
        const uint32_t kb = shb + (FL_K0 + buf * 64 * SQP) * 4;
        const uint32_t vb = shb + (FL_V0 + buf * 64 * SV) * 4;
#pragma unroll
        for (int j = 0; j < 4; j++) {
            const int c = tid + j * 256;
            const int row = c >> 4, c4 = (c & 15) * 4;
            cpa16(kb + (row * SQP + c4) * 4, ks + row * 64 + c4);
            cpa16(vb + (row * SV + c4) * 4, vs + row * 64 + c4);
        }
    };

    const int nkt = 2 * qt + 2;
    load_tile(0, 0); CP_COMMIT();

    const uint32_t* qsrc = Qg + ((size_t)bh * Tn + q0) * HDn;
    for (int i = tid; i < 128 * 16; i += 256) {
        const int row = i >> 4, c4 = (i & 15) * 4;
        *(uint4*)&Qs[row * SQP + c4] = *(const uint4*)(qsrc + row * 64 + c4);
    }
    __syncthreads();

    uint32_t aq[8][4];
#pragma unroll
    for (int k = 0; k < 8; k++) {
        aq[k][0] = Qs[(w0 + grp) * SQP + k * 8 + tig];
        aq[k][1] = Qs[(w0 + grp + 8) * SQP + k * 8 + tig];
        aq[k][2] = Qs[(w0 + grp) * SQP + k * 8 + tig + 4];
        aq[k][3] = Qs[(w0 + grp + 8) * SQP + k * 8 + tig + 4];
    }
    __syncthreads();

    float o[8][4];
#pragma unroll
    for (int n = 0; n < 8; n++)
#pragma unroll
        for (int v = 0; v < 4; v++) o[n][v] = 0.0f;
    float m0r = -1e30f, m1r = -1e30f, l0 = 0.0f, l1 = 0.0f;

    const int row0 = q0 + w0 + grp;
    const int row1 = row0 + 8;

    for (int kt = 0; kt < nkt; kt++) {
        __syncthreads();
        if (kt + 1 < nkt) load_tile(kt + 1, (kt + 1) & 1);
        CP_COMMIT();
        CP_WAIT1();
        __syncthreads();

        const uint32_t* Ks = sh + FL_K0 + (kt & 1) * 64 * SQP;
        const uint32_t* Vs = sh + FL_V0 + (kt & 1) * 64 * SV;

        const int kb = kt * 64;
        const bool active = (kb <= q0 + w0 + 15);
        if (active) {
            float s[8][4];
#pragma unroll
            for (int n = 0; n < 8; n++)
#pragma unroll
                for (int v = 0; v < 4; v++) s[n][v] = 0.0f;
#pragma unroll
            for (int k = 0; k < 8; k++) {
#pragma unroll
                for (int n = 0; n < 8; n++) {
                    const uint32_t* kp = &Ks[(n * 8 + grp) * SQP + k * 8 + tig];
                    mma_tf32(s[n], aq[k], kp[0], kp[4]);
                }
            }

            if (kb + 63 > row0) {
#pragma unroll
                for (int n = 0; n < 8; n++) {
                    const int col = kb + n * 8 + tig * 2;
                    if (col > row0)     s[n][0] = -1e30f;
                    if (col + 1 > row0) s[n][1] = -1e30f;
                    if (col > row1)     s[n][2] = -1e30f;
                    if (col + 1 > row1) s[n][3] = -1e30f;
                }
            }

            float tm0 = -1e30f, tm1 = -1e30f;
#pragma unroll
            for (int n = 0; n < 8; n++) {
                tm0 = fmaxf(tm0, fmaxf(s[n][0], s[n][1]));
                tm1 = fmaxf(tm1, fmaxf(s[n][2], s[n][3]));
            }
            tm0 = fmaxf(tm0, __shfl_xor_sync(0xffffffff, tm0, 1));
            tm0 = fmaxf(tm0, __shfl_xor_sync(0xffffffff, tm0, 2));
            tm1 = fmaxf(tm1, __shfl_xor_sync(0xffffffff, tm1, 1));
            tm1 = fmaxf(tm1, __shfl_xor_sync(0xffffffff, tm1, 2));

            const float nm0 = fmaxf(m0r, tm0);
            const float nm1 = fmaxf(m1r, tm1);
            const float c0 = __expf(m0r - nm0);
            const float c1 = __expf(m1r - nm1);
            m0r = nm0; m1r = nm1;

            float ps0 = 0.0f, ps1 = 0.0f;
            uint32_t* p0row = &Qs[(w0 + grp) * SQP];
            uint32_t* p1row = &Qs[(w0 + grp + 8) * SQP];
#pragma unroll
            for (int n = 0; n < 8; n++) {
                const float e0 = __expf(s[n][0] - nm0);
                const float e1 = __expf(s[n][1] - nm0);
                const float e2 = __expf(s[n][2] - nm1);
                const float e3 = __expf(s[n][3] - nm1);
                ps0 += e0 + e1;
                ps1 += e2 + e3;
                const int c = n * 8 + tig * 2;
                p0row[c]     = f2tf32(e0);
                p0row[c + 1] = f2tf32(e1);
                p1row[c]     = f2tf32(e2);
                p1row[c + 1] = f2tf32(e3);
            }
            ps0 += __shfl_xor_sync(0xffffffff, ps0, 1);
            ps0 += __shfl_xor_sync(0xffffffff, ps0, 2);
            ps1 += __shfl_xor_sync(0xffffffff, ps1, 1);
            ps1 += __shfl_xor_sync(0xffffffff, ps1, 2);
            l0 = l0 * c0 + ps0;
            l1 = l1 * c1 + ps1;

#pragma unroll
            for (int n = 0; n < 8; n++) {
                o[n][0] *= c0; o[n][1] *= c0;
                o[n][2] *= c1; o[n][3] *= c1;
            }
            __syncwarp();

#pragma unroll
            for (int k = 0; k < 8; k++) {
                uint32_t ap[4];
                ap[0] = Qs[(w0 + grp) * SQP + k * 8 + tig];
                ap[1] = Qs[(w0 + grp + 8) * SQP + k * 8 + tig];
                ap[2] = Qs[(w0 + grp) * SQP + k * 8 + tig + 4];
                ap[3] = Qs[(w0 + grp + 8) * SQP + k * 8 + tig + 4];
#pragma unroll
                for (int n = 0; n < 8; n++) {
                    const uint32_t b0 = Vs[(k * 8 + tig) * SV + n * 8 + grp];
                    const uint32_t b1 = Vs[(k * 8 + tig + 4) * SV + n * 8 + grp];
                    mma_tf32(o[n], ap, b0, b1);
                }
            }
            __syncwarp();
        }
    }

    // epilogue: fp16 half2 words in permuted-block layout for proj GEMM
    const float inv0 = 1.0f / l0;
    const float inv1 = 1.0f / l1;
    const int b = bh / Hn, h = bh % Hn;
    uint32_t* dst0 = Ob + (size_t)(b * Tn + row0) * RW;
    uint32_t* dst1 = dst0 + (size_t)8 * RW;
#pragma unroll
    for (int n = 0; n < 8; n++) {
        const int slot = 4 * tig + 2 * ((n >> 1) & 1) + (n & 1);
        const int word = (h * 2 + (n >> 2)) * 16 + slot;
        dst0[word] = packh2(o[n][0] * inv0, o[n][1] * inv0);
        dst1[word] = packh2(o[n][2] * inv1, o[n][3] * inv1);
    }
}

// ---------------------------------------------------------------------------
extern "C" void kernel_launch(void* const* d_in, const int* in_sizes, int n_in,
                              void* d_out, int out_size)
{
    const float* x  = (const float*)d_in[0];
    const float* Wq = (const float*)d_in[1];
    const float* bq = (const float*)d_in[2];
    const float* Wk = (const float*)d_in[3];
    const float* bk = (const float*)d_in[4];
    const float* Wv = (const float*)d_in[5];
    const float* bv = (const float*)d_in[6];
    const float* Wp = (const float*)d_in[7];
    const float* bp = (const float*)d_in[8];
    float* out = (float*)d_out;

    float *pq, *pk, *pv;
    uint32_t *pa, *pxt, *pwq, *pwk, *pwv, *pwp;
    cudaGetSymbolAddress((void**)&pq, g_q);
    cudaGetSymbolAddress((void**)&pk, g_k);
    cudaGetSymbolAddress((void**)&pv, g_v);
    cudaGetSymbolAddress((void**)&pa, g_a);
    cudaGetSymbolAddress((void**)&pxt, g_xt);
    cudaGetSymbolAddress((void**)&pwq, g_wqt);
    cudaGetSymbolAddress((void**)&pwk, g_wkt);
    cudaGetSymbolAddress((void**)&pwv, g_wvt);
    cudaGetSymbolAddress((void**)&pwp, g_wpt);

    cudaFuncSetAttribute(h16_gemm<0>,
        cudaFuncAttributeMaxDynamicSharedMemorySize, GEMM_SMEM);
    cudaFuncSetAttribute(h16_gemm<1>,
        cudaFuncAttributeMaxDynamicSharedMemorySize, GEMM_SMEM);
    cudaFuncSetAttribute(flash_tc2,
        cudaFuncAttributeMaxDynamicSharedMemorySize, FLASH_SMEM);

    prep_cvt<<<1024, 256>>>(x, Wq, Wk, Wv, Wp, pxt, pwq, pwk, pwv, pwp);

    // Fused QKV
    dim3 gq(Cn / 128, Mrows / 128, 3);   // (8, 32, 3)
    h16_gemm<0><<<gq, 256, GEMM_SMEM>>>(pxt, pwq, pwk, pwv,
                                        bq, bk, bv, pq, pk, pv);

    dim3 fg(Tn / 128, Bn * Hn);          // (16, 32)
    flash_tc2<<<fg, 256, FLASH_SMEM>>>((const uint32_t*)pq, (const uint32_t*)pk,
                                       (const uint32_t*)pv, pa);

    dim3 gp(Cn / 128, Mrows / 128, 1);   // (8, 32, 1)
    h16_gemm<1><<<gp, 256, GEMM_SMEM>>>(pa, pwp, pwp, pwp,
                                        bp, bp, bp, out, out, out);
}

// round 10
// speedup vs baseline: 2.3928x; 1.3183x over previous
#include <cuda_runtime.h>
#include <cuda_fp16.h>
#include <stdint.h>

// Problem dims
#define Bn 2
#define Tn 2048
#define Cn 1024
#define Hn 16
#define HDn 64
#define Mrows (Bn * Tn)   // 4096
#define RW 512            // words per row (1024 halfs) for GEMM operands
#define QW 32             // words per row (64 halfs) for Q/K/V

// Scratch (allocation-free: __device__ globals)
__device__ uint32_t g_q[Bn * Hn * Tn * QW];  // fp16 [B,H,T,64], pre-scaled 1/8
__device__ uint32_t g_k[Bn * Hn * Tn * QW];  // fp16
__device__ uint32_t g_v[Bn * Hn * Tn * QW];  // fp16
__device__ uint32_t g_a[Mrows * RW];         // flash out: fp16, permuted blocks
__device__ uint32_t g_xt[Mrows * RW];        // x  fp16, permuted 32-half blocks
__device__ uint32_t g_wqt[Cn * RW];          // weights fp16, permuted
__device__ uint32_t g_wkt[Cn * RW];
__device__ uint32_t g_wvt[Cn * RW];
__device__ uint32_t g_wpt[Cn * RW];

__device__ __forceinline__ uint32_t packh2(float a, float b) {
    __half2 h = __float22half2_rn(make_float2(a, b));
    return *(uint32_t*)&h;
}

// fp16 tensor mma: D(16x8 f32) += A(16x16 f16) B(16x8 f16)
__device__ __forceinline__ void mma_f16(float* c, uint32_t a0, uint32_t a1,
                                        uint32_t a2, uint32_t a3,
                                        uint32_t b0, uint32_t b1) {
    asm volatile(
        "mma.sync.aligned.m16n8k16.row.col.f32.f16.f16.f32 "
        "{%0,%1,%2,%3}, {%4,%5,%6,%7}, {%8,%9}, {%0,%1,%2,%3};"
        : "+f"(c[0]), "+f"(c[1]), "+f"(c[2]), "+f"(c[3])
        : "r"(a0), "r"(a1), "r"(a2), "r"(a3), "r"(b0), "r"(b1));
}

#define LDMX4(r0, r1, r2, r3, a) \
    asm volatile("ldmatrix.sync.aligned.m8n8.x4.shared.b16 {%0,%1,%2,%3}, [%4];" \
                 : "=r"(r0), "=r"(r1), "=r"(r2), "=r"(r3) : "r"(a))
#define LDMX4T(r0, r1, r2, r3, a) \
    asm volatile("ldmatrix.sync.aligned.m8n8.x4.trans.shared.b16 {%0,%1,%2,%3}, [%4];" \
                 : "=r"(r0), "=r"(r1), "=r"(r2), "=r"(r3) : "r"(a))

__device__ __forceinline__ void cpa16(uint32_t dst, const void* src) {
    asm volatile("cp.async.ca.shared.global [%0], [%1], 16;" :: "r"(dst), "l"(src));
}
#define CP_COMMIT() asm volatile("cp.async.commit_group;")
#define CP_WAIT1()  asm volatile("cp.async.wait_group 1;")

// ---------------------------------------------------------------------------
// prep: fp32 -> fp16 with per-32-half-block word permutation (validated R9):
//   slot(j) = (j&3)*4 + ((j>>3)&1)*2 + ((j>>2)&1)
// ---------------------------------------------------------------------------
__global__ __launch_bounds__(256)
void prep_cvt(const float* __restrict__ x,
              const float* __restrict__ wq, const float* __restrict__ wk,
              const float* __restrict__ wv, const float* __restrict__ wp,
              uint32_t* __restrict__ xt,
              uint32_t* __restrict__ wqt, uint32_t* __restrict__ wkt,
              uint32_t* __restrict__ wvt, uint32_t* __restrict__ wpt)
{
    const int i = blockIdx.x * 256 + threadIdx.x;   // 0 .. 2^18-1
    const float* src; uint32_t* dst; int off;
    if (i < (1 << 17)) { src = x; dst = xt; off = i; }
    else {
        const int j = i - (1 << 17);
        const int w = j >> 15;
        off = j & 32767;
        src = (w == 0) ? wq : (w == 1) ? wk : (w == 2) ? wv : wp;
        dst = (w == 0) ? wqt : (w == 1) ? wkt : (w == 2) ? wvt : wpt;
    }
    const float* s = src + (size_t)off * 32;
    float v[32];
#pragma unroll
    for (int q = 0; q < 8; q++) {
        float4 t = *(const float4*)(s + q * 4);
        v[q * 4 + 0] = t.x; v[q * 4 + 1] = t.y;
        v[q * 4 + 2] = t.z; v[q * 4 + 3] = t.w;
    }
    uint32_t w16[16];
#pragma unroll
    for (int j = 0; j < 16; j++) {
        const int slot = (j & 3) * 4 + (((j >> 3) & 1) << 1) + ((j >> 2) & 1);
        w16[slot] = packh2(v[2 * j], v[2 * j + 1]);
    }
    uint4* d = (uint4*)(dst + (size_t)off * 16);
#pragma unroll
    for (int q = 0; q < 4; q++)
        d[q] = make_uint4(w16[q * 4], w16[q * 4 + 1], w16[q * 4 + 2], w16[q * 4 + 3]);
}

// ---------------------------------------------------------------------------
// fp16 GEMM (validated R9): D = (A @ W^T + bias) * scale.
//   MODE 0: outputs fp16 half2 words into [B,H,T,64]   (QKV)
//   MODE 1: outputs fp32 row-major                     (projection)
// ---------------------------------------------------------------------------
#define SUBW 2048
#define STGW (4 * SUBW)
#define GEMM_SMEM (3 * STGW * 4)         // 98304 bytes

template <int MODE>
__global__ __launch_bounds__(256, 2)
void h16_gemm(const uint32_t* __restrict__ A,
              const uint32_t* __restrict__ W0, const uint32_t* __restrict__ W1,
              const uint32_t* __restrict__ W2,
              const float* __restrict__ b0p, const float* __restrict__ b1p,
              const float* __restrict__ b2p,
              void* __restrict__ D0, void* __restrict__ D1,
              void* __restrict__ D2)
{
    extern __shared__ uint32_t smem[];
    const int z = blockIdx.z;
    const uint32_t* W = (z == 0) ? W0 : ((z == 1) ? W1 : W2);
    const float* bias = (z == 0) ? b0p : ((z == 1) ? b1p : b2p);
    void* D = (z == 0) ? D0 : ((z == 1) ? D1 : D2);
    const float scale = (MODE == 0 && z == 0) ? 0.125f : 1.0f;

    const int tid  = threadIdx.x;
    const int lane = tid & 31;
    const int wid  = tid >> 5;
    const int m0   = blockIdx.y * 128;
    const int n0   = blockIdx.x * 128;
    const int wm   = (wid & 1) * 64;
    const int wn   = (wid >> 1) * 32;
    const int grp  = lane >> 2;
    const int tig  = lane & 3;

    const int lr = tid >> 1;
    const int c0 = (tid & 1) * 2;
    const uint32_t* Ag = A + (size_t)(m0 + lr) * RW;
    const uint32_t* Wg = W + (size_t)(n0 + lr) * RW;
    const uint32_t shb = (uint32_t)__cvta_generic_to_shared(smem);
    const uint32_t sw  = lr & 3;
    const uint32_t d0 = (lr * 16 + ((c0 + 0) ^ sw) * 4) * 4;
    const uint32_t d1 = (lr * 16 + ((c0 + 1) ^ sw) * 4) * 4;

    auto loadstage = [&](int it, int slot) {
        const uint32_t s0 = shb + slot * (STGW * 4);
        const uint32_t* as = Ag + it * 32 + c0 * 4;
        const uint32_t* ws = Wg + it * 32 + c0 * 4;
        cpa16(s0 + d0, as);
        cpa16(s0 + d1, as + 4);
        cpa16(s0 + SUBW * 4 + d0, as + 16);
        cpa16(s0 + SUBW * 4 + d1, as + 20);
        cpa16(s0 + 2 * SUBW * 4 + d0, ws);
        cpa16(s0 + 2 * SUBW * 4 + d1, ws + 4);
        cpa16(s0 + 3 * SUBW * 4 + d0, ws + 16);
        cpa16(s0 + 3 * SUBW * 4 + d1, ws + 20);
    };

    float acc[4][4][4];
#pragma unroll
    for (int i = 0; i < 4; i++)
#pragma unroll
        for (int j = 0; j < 4; j++)
#pragma unroll
            for (int v = 0; v < 4; v++) acc[i][j][v] = 0.0f;

    loadstage(0, 0); CP_COMMIT();
    loadstage(1, 1); CP_COMMIT();

    const int csel = (tig ^ (grp & 3)) * 4;

    for (int it = 0; it < 16; it++) {
        CP_WAIT1();
        __syncthreads();
        if (it + 2 < 16) loadstage(it + 2, (it + 2) % 3);
        CP_COMMIT();

        const uint32_t* St = smem + (it % 3) * STGW;
#pragma unroll
        for (int sub = 0; sub < 2; sub++) {
            const uint32_t* As_ = St + sub * SUBW;
            const uint32_t* Bs_ = St + 2 * SUBW + sub * SUBW;

            uint4 aA[4][2];
            uint4 bB[4];
#pragma unroll
            for (int mt = 0; mt < 4; mt++) {
                const int r = wm + mt * 16 + grp;
                aA[mt][0] = *(const uint4*)&As_[r * 16 + csel];
                aA[mt][1] = *(const uint4*)&As_[(r + 8) * 16 + csel];
            }
#pragma unroll
            for (int nt = 0; nt < 4; nt++) {
                const int r = wn + nt * 8 + grp;
                bB[nt] = *(const uint4*)&Bs_[r * 16 + csel];
            }
#pragma unroll
            for (int mt = 0; mt < 4; mt++)
#pragma unroll
                for (int nt = 0; nt < 4; nt++)
                    mma_f16(acc[mt][nt],
                            aA[mt][0].x, aA[mt][1].x, aA[mt][0].y, aA[mt][1].y,
                            bB[nt].x, bB[nt].y);
#pragma unroll
            for (int mt = 0; mt < 4; mt++)
#pragma unroll
                for (int nt = 0; nt < 4; nt++)
                    mma_f16(acc[mt][nt],
                            aA[mt][0].z, aA[mt][1].z, aA[mt][0].w, aA[mt][1].w,
                            bB[nt].z, bB[nt].w);
        }
    }

#pragma unroll
    for (int mt = 0; mt < 4; mt++) {
        const int r0 = m0 + wm + mt * 16 + grp;
#pragma unroll
        for (int nt = 0; nt < 4; nt++) {
            const int gc = n0 + wn + nt * 8 + tig * 2;
#pragma unroll
            for (int vp = 0; vp < 2; vp++) {
                const int gr = r0 + vp * 8;
                float v0 = (acc[mt][nt][vp * 2 + 0] + bias[gc]) * scale;
                float v1 = (acc[mt][nt][vp * 2 + 1] + bias[gc + 1]) * scale;
                if (MODE == 0) {
                    const int b = gr / Tn, t = gr % Tn;
                    const int h = gc >> 6, dd = gc & 63;
                    ((uint32_t*)D)[(((size_t)(b * Hn + h)) * Tn + t) * QW + (dd >> 1)] =
                        packh2(v0, v1);
                } else {
                    float2 p = {v0, v1};
                    *(float2*)&((float*)D)[(size_t)gr * Cn + gc] = p;
                }
            }
        }
    }
}

// ---------------------------------------------------------------------------
// fp16 tensor-core flash attention (causal), m16n8k16 + ldmatrix.
//   Q/K/V fp16 [bh][t][32 words]. 256 thr (8 warps), 128 q-rows, 16/warp.
//   K/V tiles of 64 keys double-buffered (cp.async). Softmax fp32.
//   Smem rows stride 36 words (ldmatrix phase conflict-free).
// ---------------------------------------------------------------------------
#define FSTR 36
#define FQ0  0                       // Q then P: 128 x 36
#define FK0  (128 * FSTR)            // 4608: 2 x (64 x 36)
#define FV0  (FK0 + 2 * 64 * FSTR)   // 9216: 2 x (64 x 36)
#define FLASH_SMEM ((FV0 + 2 * 64 * FSTR) * 4)   // 55296 bytes

__global__ __launch_bounds__(256)
void flash_h16(const uint32_t* __restrict__ Qg, const uint32_t* __restrict__ Kg,
               const uint32_t* __restrict__ Vg, uint32_t* __restrict__ Ob)
{
    extern __shared__ uint32_t sh[];
    uint32_t* Qs = sh;

    const int bh  = blockIdx.y;
    const int qt  = (gridDim.x - 1) - blockIdx.x;   // heavy tiles first
    const int tid = threadIdx.x;
    const int lane = tid & 31;
    const int wid  = tid >> 5;
    const int grp  = lane >> 2;
    const int tig  = lane & 3;
    const int q0   = qt * 128;
    const int w0   = wid * 16;

    const uint32_t shb = (uint32_t)__cvta_generic_to_shared(sh);
    const uint32_t* Kbh = Kg + (size_t)bh * Tn * QW;
    const uint32_t* Vbh = Vg + (size_t)bh * Tn * QW;

    auto load_tile = [&](int kt, int buf) {
        const uint32_t* ks = Kbh + (size_t)kt * 64 * QW;
        const uint32_t* vs = Vbh + (size_t)kt * 64 * QW;
        const uint32_t kb = shb + (FK0 + buf * 64 * FSTR) * 4;
        const uint32_t vb = shb + (FV0 + buf * 64 * FSTR) * 4;
#pragma unroll
        for (int j = 0; j < 2; j++) {
            const int c = tid + j * 256;          // 0..511 chunks
            const int row = c >> 3, c4 = (c & 7) * 4;
            cpa16(kb + (row * FSTR + c4) * 4, ks + row * QW + c4);
            cpa16(vb + (row * FSTR + c4) * 4, vs + row * QW + c4);
        }
    };

    const int nkt = 2 * qt + 2;
    load_tile(0, 0); CP_COMMIT();

    // stage Q (fp16, raw copy)
    const uint32_t* qsrc = Qg + ((size_t)bh * Tn + q0) * QW;
#pragma unroll
    for (int j = 0; j < 4; j++) {
        const int i = tid + j * 256;              // 0..1023 chunks
        const int row = i >> 3, c4 = (i & 7) * 4;
        *(uint4*)&Qs[row * FSTR + c4] = *(const uint4*)(qsrc + row * QW + c4);
    }
    __syncthreads();

    // Q fragments via ldmatrix x4: aq[kk] = {a0,a1,a2,a3} for d-step kk
    uint32_t aq[4][4];
    {
        const uint32_t abase = shb +
            ((w0 + (lane & 7) + 8 * ((lane >> 3) & 1)) * FSTR + 4 * (lane >> 4)) * 4;
#pragma unroll
        for (int kk = 0; kk < 4; kk++)
            LDMX4(aq[kk][0], aq[kk][1], aq[kk][2], aq[kk][3], abase + kk * 32);
    }
    __syncthreads();   // Qs now reusable as P

    float o[8][4];
#pragma unroll
    for (int n = 0; n < 8; n++)
#pragma unroll
        for (int v = 0; v < 4; v++) o[n][v] = 0.0f;
    float m0r = -1e30f, m1r = -1e30f, l0 = 0.0f, l1 = 0.0f;

    const int row0 = q0 + w0 + grp;
    const int row1 = row0 + 8;

    // per-lane ldmatrix base offsets (words)
    const int kvrow = (lane & 7) + 8 * ((lane >> 3) & 1);   // K: row-in-16-group
    const int kcol  = 4 * (lane >> 4);                      // unused halves selector
    const int vrow  = (lane & 7) + 8 * ((lane >> 3) & 1);
    const int vcol  = 4 * (lane >> 4);

    for (int kt = 0; kt < nkt; kt++) {
        __syncthreads();
        if (kt + 1 < nkt) load_tile(kt + 1, (kt + 1) & 1);
        CP_COMMIT();
        CP_WAIT1();
        __syncthreads();

        const uint32_t ksb = shb + (FK0 + (kt & 1) * 64 * FSTR) * 4;
        const uint32_t vsb = shb + (FV0 + (kt & 1) * 64 * FSTR) * 4;

        const int kb = kt * 64;
        const bool active = (kb <= q0 + w0 + 15);
        if (active) {
            // ---- S = Q K^T ----
            float s[8][4];
#pragma unroll
            for (int n = 0; n < 8; n++)
#pragma unroll
                for (int v = 0; v < 4; v++) s[n][v] = 0.0f;
#pragma unroll
            for (int kk = 0; kk < 4; kk++) {
#pragma unroll
                for (int ntp = 0; ntp < 4; ntp++) {
                    uint32_t r0, r1, r2, r3;
                    // K rows ntp*16 + kvrow', word kk*8 + 4*((lane>>3)&1)
                    const uint32_t ka = ksb +
                        (((ntp * 16) + (lane & 7) + 8 * (lane >> 4)) * FSTR
                         + kk * 8 + 4 * ((lane >> 3) & 1)) * 4;
                    LDMX4(r0, r1, r2, r3, ka);
                    mma_f16(s[2 * ntp], aq[kk][0], aq[kk][1], aq[kk][2], aq[kk][3], r0, r1);
                    mma_f16(s[2 * ntp + 1], aq[kk][0], aq[kk][1], aq[kk][2], aq[kk][3], r2, r3);
                }
            }

            // ---- causal mask ----
            if (kb + 63 > row0) {
#pragma unroll
                for (int n = 0; n < 8; n++) {
                    const int col = kb + n * 8 + tig * 2;
                    if (col > row0)     s[n][0] = -1e30f;
                    if (col + 1 > row0) s[n][1] = -1e30f;
                    if (col > row1)     s[n][2] = -1e30f;
                    if (col + 1 > row1) s[n][3] = -1e30f;
                }
            }

            // ---- online softmax (fp32) ----
            float tm0 = -1e30f, tm1 = -1e30f;
#pragma unroll
            for (int n = 0; n < 8; n++) {
                tm0 = fmaxf(tm0, fmaxf(s[n][0], s[n][1]));
                tm1 = fmaxf(tm1, fmaxf(s[n][2], s[n][3]));
            }
            tm0 = fmaxf(tm0, __shfl_xor_sync(0xffffffff, tm0, 1));
            tm0 = fmaxf(tm0, __shfl_xor_sync(0xffffffff, tm0, 2));
            tm1 = fmaxf(tm1, __shfl_xor_sync(0xffffffff, tm1, 1));
            tm1 = fmaxf(tm1, __shfl_xor_sync(0xffffffff, tm1, 2));

            const float nm0 = fmaxf(m0r, tm0);
            const float nm1 = fmaxf(m1r, tm1);
            const float c0 = __expf(m0r - nm0);
            const float c1 = __expf(m1r - nm1);
            m0r = nm0; m1r = nm1;

            float ps0 = 0.0f, ps1 = 0.0f;
            uint32_t* p0row = &Qs[(w0 + grp) * FSTR];
            uint32_t* p1row = &Qs[(w0 + grp + 8) * FSTR];
#pragma unroll
            for (int n = 0; n < 8; n++) {
                const float e0 = __expf(s[n][0] - nm0);
                const float e1 = __expf(s[n][1] - nm0);
                const float e2 = __expf(s[n][2] - nm1);
                const float e3 = __expf(s[n][3] - nm1);
                ps0 += e0 + e1;
                ps1 += e2 + e3;
                p0row[4 * n + tig] = packh2(e0, e1);
                p1row[4 * n + tig] = packh2(e2, e3);
            }
            ps0 += __shfl_xor_sync(0xffffffff, ps0, 1);
            ps0 += __shfl_xor_sync(0xffffffff, ps0, 2);
            ps1 += __shfl_xor_sync(0xffffffff, ps1, 1);
            ps1 += __shfl_xor_sync(0xffffffff, ps1, 2);
            l0 = l0 * c0 + ps0;
            l1 = l1 * c1 + ps1;

#pragma unroll
            for (int n = 0; n < 8; n++) {
                o[n][0] *= c0; o[n][1] *= c0;
                o[n][2] *= c1; o[n][3] *= c1;
            }
            __syncwarp();

            // ---- O += P V ----
            const uint32_t pbase = shb +
                ((w0 + (lane & 7) + 8 * ((lane >> 3) & 1)) * FSTR + 4 * (lane >> 4)) * 4;
#pragma unroll
            for (int kk = 0; kk < 4; kk++) {
                uint32_t ap0, ap1, ap2, ap3;
                LDMX4(ap0, ap1, ap2, ap3, pbase + kk * 32);
#pragma unroll
                for (int np = 0; np < 4; np++) {
                    uint32_t r0, r1, r2, r3;
                    const uint32_t va = vsb +
                        ((kk * 16 + vrow) * FSTR + np * 8 + vcol) * 4;
                    LDMX4T(r0, r1, r2, r3, va);
                    mma_f16(o[2 * np], ap0, ap1, ap2, ap3, r0, r1);
                    mma_f16(o[2 * np + 1], ap0, ap1, ap2, ap3, r2, r3);
                }
            }
            __syncwarp();
        }
    }

    // ---- epilogue: fp16 permuted-block layout for proj GEMM (validated R9)
    const float inv0 = 1.0f / l0;
    const float inv1 = 1.0f / l1;
    const int b = bh / Hn, h = bh % Hn;
    uint32_t* dst0 = Ob + (size_t)(b * Tn + row0) * RW;
    uint32_t* dst1 = dst0 + (size_t)8 * RW;
#pragma unroll
    for (int n = 0; n < 8; n++) {
        const int slot = 4 * tig + 2 * ((n >> 1) & 1) + (n & 1);
        const int word = (h * 2 + (n >> 2)) * 16 + slot;
        dst0[word] = packh2(o[n][0] * inv0, o[n][1] * inv0);
        dst1[word] = packh2(o[n][2] * inv1, o[n][3] * inv1);
    }
}

// ---------------------------------------------------------------------------
extern "C" void kernel_launch(void* const* d_in, const int* in_sizes, int n_in,
                              void* d_out, int out_size)
{
    const float* x  = (const float*)d_in[0];
    const float* Wq = (const float*)d_in[1];
    const float* bq = (const float*)d_in[2];
    const float* Wk = (const float*)d_in[3];
    const float* bk = (const float*)d_in[4];
    const float* Wv = (const float*)d_in[5];
    const float* bv = (const float*)d_in[6];
    const float* Wp = (const float*)d_in[7];
    const float* bp = (const float*)d_in[8];
    float* out = (float*)d_out;

    uint32_t *pq, *pk, *pv, *pa, *pxt, *pwq, *pwk, *pwv, *pwp;
    cudaGetSymbolAddress((void**)&pq, g_q);
    cudaGetSymbolAddress((void**)&pk, g_k);
    cudaGetSymbolAddress((void**)&pv, g_v);
    cudaGetSymbolAddress((void**)&pa, g_a);
    cudaGetSymbolAddress((void**)&pxt, g_xt);
    cudaGetSymbolAddress((void**)&pwq, g_wqt);
    cudaGetSymbolAddress((void**)&pwk, g_wkt);
    cudaGetSymbolAddress((void**)&pwv, g_wvt);
    cudaGetSymbolAddress((void**)&pwp, g_wpt);

    cudaFuncSetAttribute(h16_gemm<0>,
        cudaFuncAttributeMaxDynamicSharedMemorySize, GEMM_SMEM);
    cudaFuncSetAttribute(h16_gemm<1>,
        cudaFuncAttributeMaxDynamicSharedMemorySize, GEMM_SMEM);
    cudaFuncSetAttribute(flash_h16,
        cudaFuncAttributeMaxDynamicSharedMemorySize, FLASH_SMEM);

    prep_cvt<<<1024, 256>>>(x, Wq, Wk, Wv, Wp, pxt, pwq, pwk, pwv, pwp);

    // Fused QKV
    dim3 gq(Cn / 128, Mrows / 128, 3);   // (8, 32, 3)
    h16_gemm<0><<<gq, 256, GEMM_SMEM>>>(pxt, pwq, pwk, pwv,
                                        bq, bk, bv, pq, pk, pv);

    dim3 fg(Tn / 128, Bn * Hn);          // (16, 32)
    flash_h16<<<fg, 256, FLASH_SMEM>>>(pq, pk, pv, pa);

    dim3 gp(Cn / 128, Mrows / 128, 1);   // (8, 32, 1)
    h16_gemm<1><<<gp, 256, GEMM_SMEM>>>(pa, pwp, pwp, pwp,
                                        bp, bp, bp, out, out, out);
}